// round 13
// baseline (speedup 1.0000x reference)
#include <cuda_runtime.h>
#include <cuda_fp16.h>
#include <math.h>

#define NP 16384
#define NR 8192

typedef unsigned long long ull;

// ============================ scratch buffers ============================
__device__ __align__(16) __half g_xcatH[(size_t)NP * 384];
__device__ __align__(16) __half g_xcatL[(size_t)NP * 384];
__device__ __align__(16) __half g_h1H  [(size_t)NP * 384];
__device__ __align__(16) __half g_h1L  [(size_t)NP * 384];
__device__ __align__(16) __half g_buf2H[(size_t)NP * 256];   // cols 0-127 cc2, 128-255 maxfeat
__device__ __align__(16) __half g_buf2L[(size_t)NP * 256];
__device__ __align__(16) __half g_co1H [(size_t)NP * 256];
__device__ __align__(16) __half g_co1L [(size_t)NP * 256];
__device__ __align__(16) __half g_fullH[(size_t)NP * 160];   // cols 0-31 pcd, 32-159 attach
__device__ __align__(16) __half g_fullL[(size_t)NP * 160];
__device__ __align__(16) __half g_d1H  [(size_t)NP * 160];
__device__ __align__(16) __half g_d1L  [(size_t)NP * 160];
__device__ __align__(16) __half g_d2H  [(size_t)NP * 160];
__device__ __align__(16) __half g_d2L  [(size_t)NP * 160];
__device__ __align__(16) __half g_fpH  [(size_t)NP * 128];
__device__ __align__(16) __half g_fpL  [(size_t)NP * 128];
__device__ __align__(16) float  g_fpF  [(size_t)NP * 128];
__device__ __align__(16) float  g_s1F  [(size_t)NP * 128];
__device__ __align__(16) __half g_rgbTH[(size_t)NR * 128];
__device__ __align__(16) __half g_rgbTL[(size_t)NR * 128];
__device__ int g_idx[NP * 3];
#define WTOT 397312
__device__ __align__(16) __half g_whi[WTOT];
__device__ __align__(16) __half g_wlo[WTOT];

// ============================ helpers ============================
__device__ __forceinline__ void splitf(float x, __half& h, __half& l) {
    h = __float2half(x);
    l = __float2half(x - __half2float(h));
}
__device__ __forceinline__ void mma16816(float* d, const unsigned* a, const unsigned* b) {
    asm volatile("mma.sync.aligned.m16n8k16.row.col.f32.f16.f16.f32 "
        "{%0,%1,%2,%3}, {%4,%5,%6,%7}, {%8,%9}, {%0,%1,%2,%3};"
        : "+f"(d[0]), "+f"(d[1]), "+f"(d[2]), "+f"(d[3])
        : "r"(a[0]), "r"(a[1]), "r"(a[2]), "r"(a[3]), "r"(b[0]), "r"(b[1]));
}
__device__ __forceinline__ void ldm4(unsigned* r, unsigned addr) {
    asm volatile("ldmatrix.sync.aligned.m8n8.x4.shared.b16 {%0,%1,%2,%3}, [%4];"
        : "=r"(r[0]), "=r"(r[1]), "=r"(r[2]), "=r"(r[3]) : "r"(addr));
}
__device__ __forceinline__ void cpa16(unsigned dst, const void* src) {
    asm volatile("cp.async.cg.shared.global [%0], [%1], 16;" :: "r"(dst), "l"(src));
}
__device__ __forceinline__ void cpa_commit() {
    asm volatile("cp.async.commit_group;" ::: "memory");
}
__device__ __forceinline__ void cpa_wait0() {
    asm volatile("cp.async.wait_group 0;" ::: "memory");
}

// ============================ fused prep: weight split + rgb transpose ============================
#define PREP_BLKS ((WTOT + 255) / 256)
__global__ void prep_misc(
    const float* __restrict__ cc1, const float* __restrict__ cc2,
    const float* __restrict__ co1, const float* __restrict__ co2,
    const float* __restrict__ dh1, const float* __restrict__ dh2,
    const float* __restrict__ dh3, const float* __restrict__ sh1,
    __half* __restrict__ dhi, __half* __restrict__ dlo,
    const float* __restrict__ rgbf,
    __half* __restrict__ rgbTH, __half* __restrict__ rgbTL)
{
    int bid = blockIdx.x;
    if (bid < PREP_BLKS) {
        int g = bid * 256 + threadIdx.y * 32 + threadIdx.x;
        if (g >= WTOT) return;
        const float* src; int loc, K, Kpad;
        if      (g < 147456) { src = cc1; loc = g;          K = 384; Kpad = 384; }
        else if (g < 196608) { src = cc2; loc = g - 147456; K = 384; Kpad = 384; }
        else if (g < 262144) { src = co1; loc = g - 196608; K = 256; Kpad = 256; }
        else if (g < 294912) { src = co2; loc = g - 262144; K = 256; Kpad = 256; }
        else if (g < 325632) { src = dh1; loc = g - 294912; K = 160; Kpad = 192; }
        else if (g < 356352) { src = dh2; loc = g - 325632; K = 160; Kpad = 192; }
        else if (g < 380928) { src = dh3; loc = g - 356352; K = 160; Kpad = 192; }
        else                 { src = sh1; loc = g - 380928; K = 128; Kpad = 128; }
        int r = loc / Kpad, c = loc - r * Kpad;
        float x = (c < K) ? src[r * K + c] : 0.f;
        __half h, l; splitf(x, h, l);
        dhi[g] = h; dlo[g] = l;
    } else {
        __shared__ float tile[32][33];
        int b2 = bid - PREP_BLKS;
        int c0 = (b2 >> 8) * 32;
        int n0 = (b2 & 255) * 32;
        #pragma unroll
        for (int i = 0; i < 32; i += 8)
            tile[threadIdx.y + i][threadIdx.x] = rgbf[(c0 + threadIdx.y + i) * NR + n0 + threadIdx.x];
        __syncthreads();
        #pragma unroll
        for (int i = 0; i < 32; i += 8) {
            float v = tile[threadIdx.x][threadIdx.y + i];
            __half h, l; splitf(v, h, l);
            size_t o = (size_t)(n0 + threadIdx.y + i) * 128 + c0 + threadIdx.x;
            rgbTH[o] = h; rgbTL[o] = l;
        }
    }
}

// ============================ 3-NN ============================
__global__ __launch_bounds__(256) void knn_kernel(const float* __restrict__ pcd,
                                                  const float* __restrict__ rgb,
                                                  int* __restrict__ outIdx)
{
    __shared__ float4 srgb[2048];
    __shared__ float  md[256 * 3];
    __shared__ int    mi[256 * 3];
    int tid = threadIdx.x;
    int p = blockIdx.x * 128 + (tid & 127);
    int half = tid >> 7;
    float px = pcd[p * 3 + 0], py = pcd[p * 3 + 1], pz = pcd[p * 3 + 2];
    float b0 = 1e30f, b1 = 1e30f, b2 = 1e30f;
    int i0 = 0, i1 = 0, i2 = 0;
    for (int r = 0; r < 4; r++) {
        __syncthreads();
        for (int q = tid; q < 2048; q += 256) {
            int j = (q >= 1024 ? 3072 : 0) + r * 1024 + q;
            srgb[q] = make_float4(rgb[j * 3 + 0], rgb[j * 3 + 1], rgb[j * 3 + 2], 0.f);
        }
        __syncthreads();
        const float4* tile = srgb + half * 1024;
        int base = half * 4096 + r * 1024;
        #pragma unroll 8
        for (int q = 0; q < 1024; q++) {
            float4 rr = tile[q];
            float dx = px - rr.x, dy = py - rr.y, dz = pz - rr.z;
            float d2 = dx * dx; d2 = fmaf(dy, dy, d2); d2 = fmaf(dz, dz, d2);
            if (d2 < b2) {
                int idx = base + q;
                if (d2 < b0)      { b2 = b1; i2 = i1; b1 = b0; i1 = i0; b0 = d2; i0 = idx; }
                else if (d2 < b1) { b2 = b1; i2 = i1; b1 = d2; i1 = idx; }
                else              { b2 = d2; i2 = idx; }
            }
        }
    }
    md[tid * 3 + 0] = b0; md[tid * 3 + 1] = b1; md[tid * 3 + 2] = b2;
    mi[tid * 3 + 0] = i0; mi[tid * 3 + 1] = i1; mi[tid * 3 + 2] = i2;
    __syncthreads();
    if (tid < 128) {
        float a[3] = {b0, b1, b2}; int ai[3] = {i0, i1, i2};
        float bb[3] = {md[(tid + 128) * 3], md[(tid + 128) * 3 + 1], md[(tid + 128) * 3 + 2]};
        int bi[3] = {mi[(tid + 128) * 3], mi[(tid + 128) * 3 + 1], mi[(tid + 128) * 3 + 2]};
        int ia = 0, ib = 0;
        #pragma unroll
        for (int t = 0; t < 3; t++) {
            bool tA = (ib >= 3) || (ia < 3 && a[ia] <= bb[ib]);
            float rd = tA ? a[ia] : bb[ib];
            int ri = tA ? ai[ia] : bi[ib];
            if (tA) ia++; else ib++;
            outIdx[p * 3 + t] = (sqrtf(rd) > 0.075f) ? -1 : ri;
        }
    }
}

// ============================ staging kernels ============================
__global__ void tpose_pcd(const float* __restrict__ in,
                          __half* __restrict__ outH, __half* __restrict__ outL)
{
    __shared__ float t[32][33];
    int n0 = blockIdx.x * 32;
    int tx = threadIdx.x, ty = threadIdx.y;
    #pragma unroll
    for (int i = 0; i < 32; i += 8) t[ty + i][tx] = in[(ty + i) * NP + n0 + tx];
    __syncthreads();
    #pragma unroll
    for (int i = 0; i < 32; i += 8) {
        float v = t[tx][ty + i];
        __half h, l; splitf(v, h, l);
        size_t o = (size_t)(n0 + ty + i) * 160 + tx;
        outH[o] = h; outL[o] = l;
    }
}

__global__ __launch_bounds__(256) void gather_kernel(
    const __half* __restrict__ rgbTH, const __half* __restrict__ rgbTL,
    const int* __restrict__ idx,
    __half* __restrict__ xcatH, __half* __restrict__ xcatL)
{
    int e = blockIdx.x * 256 + threadIdx.x;
    int c4 = e & 31;
    int t = e >> 5;
    int p = t / 3, j = t - p * 3;
    int row = idx[p * 3 + j];
    uint2 vh = make_uint2(0u, 0u), vl = make_uint2(0u, 0u);
    if (row >= 0) {
        vh = *(const uint2*)(rgbTH + (size_t)row * 128 + c4 * 4);
        vl = *(const uint2*)(rgbTL + (size_t)row * 128 + c4 * 4);
    }
    size_t o = (size_t)p * 384 + j * 128 + c4 * 4;
    *(uint2*)(xcatH + o) = vh;
    *(uint2*)(xcatL + o) = vl;
}

__global__ __launch_bounds__(256) void maxfeat_kernel(
    const __half* __restrict__ rgbTH, const __half* __restrict__ rgbTL,
    const int* __restrict__ idx,
    __half* __restrict__ buf2H, __half* __restrict__ buf2L)
{
    int e = blockIdx.x * 256 + threadIdx.x;
    int c4 = e & 31;
    int p = e >> 5;
    float m[4] = {-1e30f, -1e30f, -1e30f, -1e30f};
    #pragma unroll
    for (int j = 0; j < 3; j++) {
        int row = idx[p * 3 + j];
        float v[4] = {0.f, 0.f, 0.f, 0.f};
        if (row >= 0) {
            const __half* ph = rgbTH + (size_t)row * 128 + c4 * 4;
            const __half* pl = rgbTL + (size_t)row * 128 + c4 * 4;
            #pragma unroll
            for (int q = 0; q < 4; q++)
                v[q] = __half2float(ph[q]) + __half2float(pl[q]);
        }
        #pragma unroll
        for (int q = 0; q < 4; q++) m[q] = fmaxf(m[q], v[q]);
    }
    __half hh[4], ll[4];
    #pragma unroll
    for (int q = 0; q < 4; q++) splitf(m[q], hh[q], ll[q]);
    size_t o = (size_t)p * 256 + 128 + c4 * 4;
    *(__half2*)(buf2H + o)     = __halves2half2(hh[0], hh[1]);
    *(__half2*)(buf2H + o + 2) = __halves2half2(hh[2], hh[3]);
    *(__half2*)(buf2L + o)     = __halves2half2(ll[0], ll[1]);
    *(__half2*)(buf2L + o + 2) = __halves2half2(ll[2], ll[3]);
}

// ============================ HMMA GEMM (128x128, cp.async, ldmatrix, term-major) ============================
// Y[p, m] = sum_k X[p,k] * W[m,k]; X/W fp16 hi/lo planes; acc = XhWh + XlWh + XhWl (fp32).
// block 128x128, 8 warps (warp 32x64), K-slab 32, 2-stage cp.async, ldmatrix fragments.
// MMA emission is term-major so same-accumulator MMAs are spaced 4 apart (breaks RAW stalls).
#define LDW 40
#define PLANE (128 * LDW)
#define STG   (4 * PLANE)
#define AH 0
#define AL PLANE
#define BH (2 * PLANE)
#define BL (3 * PLANE)
__global__ __launch_bounds__(256, 2) void gemm_hmma(
    const __half* __restrict__ Xh, const __half* __restrict__ Xl, int pitchA, int K,
    const __half* __restrict__ Whi, const __half* __restrict__ Wlo, int Wpitch, int Cout,
    __half* __restrict__ Yh, __half* __restrict__ Yl, int pitchY,
    float* __restrict__ Yf, int pitchYf,
    const float* __restrict__ bias, const float* __restrict__ bn, int mode)
{
    extern __shared__ __half sdyn[];
    __shared__ float sSc[128], sSh[128];

    const int tid = threadIdx.x;
    const int lane = tid & 31, wid = tid >> 5;
    const int wm = wid >> 1, wn = wid & 1;
    const int g = lane >> 2, tc = lane & 3;
    const int n0 = blockIdx.x * 128;
    const int nb0 = blockIdx.y * 128;
    const int NT = min(128, Cout - nb0);

    if (tid < 128) {
        float sc = 0.f, sh = 0.f;
        if (tid < NT) {
            int m = nb0 + tid;
            float b = bias[m];
            sc = 1.f; sh = b;
            if (mode) {
                float gg = bn[m], be = bn[Cout + m], mn = bn[2 * Cout + m], v = bn[3 * Cout + m];
                float inv = gg * rsqrtf(v + 1e-5f);
                sc = inv; sh = (b - mn) * inv + be;
            }
        }
        sSc[tid] = sc; sSh[tid] = sh;
    }

    float acc[2][8][4];
    #pragma unroll
    for (int a = 0; a < 2; a++)
        #pragma unroll
        for (int b = 0; b < 8; b++)
            #pragma unroll
            for (int c = 0; c < 4; c++) acc[a][b][c] = 0.f;

    const int r0c = tid >> 2,         o0c = (tid & 3) * 8;
    const int r1c = (tid + 256) >> 2, o1c = ((tid + 256) & 3) * 8;
    const unsigned sbase = (unsigned)__cvta_generic_to_shared(sdyn);

    const int slabs = K >> 5;

    #define LOAD_SLAB(sl) do {                                                      \
        int k0_ = (sl) << 5;                                                        \
        unsigned sb_ = sbase + ((sl) & 1) * (STG * 2);                              \
        cpa16(sb_ + (AH + r0c * LDW + o0c) * 2, Xh + (size_t)(n0 + r0c) * pitchA + k0_ + o0c);  \
        cpa16(sb_ + (AH + r1c * LDW + o1c) * 2, Xh + (size_t)(n0 + r1c) * pitchA + k0_ + o1c);  \
        cpa16(sb_ + (AL + r0c * LDW + o0c) * 2, Xl + (size_t)(n0 + r0c) * pitchA + k0_ + o0c);  \
        cpa16(sb_ + (AL + r1c * LDW + o1c) * 2, Xl + (size_t)(n0 + r1c) * pitchA + k0_ + o1c);  \
        cpa16(sb_ + (BH + r0c * LDW + o0c) * 2, Whi + (size_t)(nb0 + r0c) * Wpitch + k0_ + o0c); \
        cpa16(sb_ + (BH + r1c * LDW + o1c) * 2, Whi + (size_t)(nb0 + r1c) * Wpitch + k0_ + o1c); \
        cpa16(sb_ + (BL + r0c * LDW + o0c) * 2, Wlo + (size_t)(nb0 + r0c) * Wpitch + k0_ + o0c); \
        cpa16(sb_ + (BL + r1c * LDW + o1c) * 2, Wlo + (size_t)(nb0 + r1c) * Wpitch + k0_ + o1c); \
        cpa_commit();                                                               \
    } while (0)

    const int arow = wm * 32 + (lane & 15);
    const int akk0 = (lane >> 4) * 8;
    const int brow = wn * 64 + ((lane >> 4) << 3) + (lane & 7);
    const int bkk0 = ((lane >> 3) & 1) * 8;

    LOAD_SLAB(0);
    for (int sl = 0; sl < slabs; sl++) {
        cpa_wait0();
        __syncthreads();
        if (sl + 1 < slabs) LOAD_SLAB(sl + 1);

        const unsigned stb = sbase + (sl & 1) * (STG * 2);
        #pragma unroll
        for (int s = 0; s < 2; s++) {
            const int akk = s * 16 + akk0;
            const int bkk = s * 16 + bkk0;
            unsigned ah[2][4], al[2][4];
            #pragma unroll
            for (int mt = 0; mt < 2; mt++) {
                unsigned off = ((arow + mt * 16) * LDW + akk) * 2;
                ldm4(ah[mt], stb + (AH * 2) + off);
                ldm4(al[mt], stb + (AL * 2) + off);
            }
            #pragma unroll
            for (int jp = 0; jp < 4; jp++) {
                unsigned boff = ((brow + jp * 16) * LDW + bkk) * 2;
                unsigned bh[4], bl[4];
                ldm4(bh, stb + (BH * 2) + boff);
                ldm4(bl, stb + (BL * 2) + boff);
                // term-major: same acc[mt][nt] recurs at distance 4 (h x mt), not 1
                #pragma unroll
                for (int t = 0; t < 3; t++) {
                    #pragma unroll
                    for (int h = 0; h < 2; h++) {
                        int nt = jp * 2 + h;
                        #pragma unroll
                        for (int mt = 0; mt < 2; mt++) {
                            const unsigned* aa = (t == 1) ? al[mt] : ah[mt];
                            const unsigned* bb = (t == 2) ? (bl + 2 * h) : (bh + 2 * h);
                            mma16816(acc[mt][nt], aa, bb);
                        }
                    }
                }
            }
        }
        __syncthreads();
    }

    // --- epilogue ---
    #pragma unroll
    for (int mt = 0; mt < 2; mt++) {
        int r0 = n0 + wm * 32 + mt * 16 + g;
        #pragma unroll
        for (int nt = 0; nt < 8; nt++) {
            int col = wn * 64 + nt * 8 + tc * 2;
            if (col < NT) {
                float sc0 = sSc[col], sh0 = sSh[col];
                float sc1 = sSc[col + 1], sh1 = sSh[col + 1];
                float* a = acc[mt][nt];
                float y0 = a[0] * sc0 + sh0;
                float y1 = a[1] * sc1 + sh1;
                float y2 = a[2] * sc0 + sh0;
                float y3 = a[3] * sc1 + sh1;
                if (mode) {
                    y0 = fmaxf(y0, 0.f); y1 = fmaxf(y1, 0.f);
                    y2 = fmaxf(y2, 0.f); y3 = fmaxf(y3, 0.f);
                }
                if (Yf) {
                    *(float2*)(Yf + (size_t)r0 * pitchYf + nb0 + col)       = make_float2(y0, y1);
                    *(float2*)(Yf + (size_t)(r0 + 8) * pitchYf + nb0 + col) = make_float2(y2, y3);
                }
                if (Yh) {
                    __half h0, l0, h1, l1, h2, l2, h3, l3;
                    splitf(y0, h0, l0); splitf(y1, h1, l1);
                    splitf(y2, h2, l2); splitf(y3, h3, l3);
                    *(__half2*)(Yh + (size_t)r0 * pitchY + nb0 + col)       = __halves2half2(h0, h1);
                    *(__half2*)(Yh + (size_t)(r0 + 8) * pitchY + nb0 + col) = __halves2half2(h2, h3);
                    *(__half2*)(Yl + (size_t)r0 * pitchY + nb0 + col)       = __halves2half2(l0, l1);
                    *(__half2*)(Yl + (size_t)(r0 + 8) * pitchY + nb0 + col) = __halves2half2(l2, l3);
                }
            }
        }
    }
}

// ============================ heads ============================
__global__ __launch_bounds__(256) void score_kernel(const float* __restrict__ s,
                                                    const float* __restrict__ w,
                                                    const float* __restrict__ b,
                                                    float* __restrict__ out)
{
    int wid = threadIdx.x >> 5, lid = threadIdx.x & 31;
    int p = blockIdx.x * 8 + wid;
    float4 v = *(const float4*)(s + (size_t)p * 128 + lid * 4);
    float4 ww = *(const float4*)(w + lid * 4);
    float sum = v.x * ww.x + v.y * ww.y + v.z * ww.z + v.w * ww.w;
    #pragma unroll
    for (int o = 16; o > 0; o >>= 1) sum += __shfl_xor_sync(0xffffffff, sum, o);
    if (lid == 0) out[p] = 1.f / (1.f + expf(-(sum + b[0])));
}

__global__ __launch_bounds__(256) void normalize_kernel(const float* __restrict__ fp,
                                                        float* __restrict__ out)
{
    int wid = threadIdx.x >> 5, lid = threadIdx.x & 31;
    int p = blockIdx.x * 8 + wid;
    float4 v = *(const float4*)(fp + (size_t)p * 128 + lid * 4);
    float ss = v.x * v.x + v.y * v.y + v.z * v.z + v.w * v.w;
    #pragma unroll
    for (int o = 16; o > 0; o >>= 1) ss += __shfl_xor_sync(0xffffffff, ss, o);
    float inv = 1.f / fmaxf(sqrtf(ss), 1e-12f);
    float4 r = make_float4(v.x * inv, v.y * inv, v.z * inv, v.w * inv);
    *(float4*)(out + (size_t)p * 128 + lid * 4) = r;
}

// ============================ launch ============================
extern "C" void kernel_launch(void* const* d_in, const int* in_sizes, int n_in,
                              void* d_out, int out_size)
{
    const float* pcd_xyz  = (const float*)d_in[0];
    const float* rgb_xyz  = (const float*)d_in[1];
    const float* pcd_feat = (const float*)d_in[2];
    const float* rgb_feat = (const float*)d_in[3];
    const float* cc1_w = (const float*)d_in[4];
    const float* cc1_b = (const float*)d_in[5];
    const float* cc_bn = (const float*)d_in[6];
    const float* cc2_w = (const float*)d_in[7];
    const float* cc2_b = (const float*)d_in[8];
    const float* co1_w = (const float*)d_in[9];
    const float* co1_b = (const float*)d_in[10];
    const float* co_bn = (const float*)d_in[11];
    const float* co2_w = (const float*)d_in[12];
    const float* co2_b = (const float*)d_in[13];
    const float* dh1_w = (const float*)d_in[14];
    const float* dh1_b = (const float*)d_in[15];
    const float* dh1_bn = (const float*)d_in[16];
    const float* dh2_w = (const float*)d_in[17];
    const float* dh2_b = (const float*)d_in[18];
    const float* dh2_bn = (const float*)d_in[19];
    const float* dh3_w = (const float*)d_in[20];
    const float* dh3_b = (const float*)d_in[21];
    const float* sh1_w = (const float*)d_in[22];
    const float* sh1_b = (const float*)d_in[23];
    const float* sh_bn = (const float*)d_in[24];
    const float* sh2_w = (const float*)d_in[25];
    const float* sh2_b = (const float*)d_in[26];

    __half *xcH, *xcL, *h1H, *h1L, *b2H, *b2L, *coH, *coL, *fuH, *fuL;
    __half *d1H, *d1L, *d2H, *d2L, *fpH, *fpL, *rgH, *rgL, *whi, *wlo;
    float *fpF, *s1F;
    int* idx;
    cudaGetSymbolAddress((void**)&xcH, g_xcatH); cudaGetSymbolAddress((void**)&xcL, g_xcatL);
    cudaGetSymbolAddress((void**)&h1H, g_h1H);   cudaGetSymbolAddress((void**)&h1L, g_h1L);
    cudaGetSymbolAddress((void**)&b2H, g_buf2H); cudaGetSymbolAddress((void**)&b2L, g_buf2L);
    cudaGetSymbolAddress((void**)&coH, g_co1H);  cudaGetSymbolAddress((void**)&coL, g_co1L);
    cudaGetSymbolAddress((void**)&fuH, g_fullH); cudaGetSymbolAddress((void**)&fuL, g_fullL);
    cudaGetSymbolAddress((void**)&d1H, g_d1H);   cudaGetSymbolAddress((void**)&d1L, g_d1L);
    cudaGetSymbolAddress((void**)&d2H, g_d2H);   cudaGetSymbolAddress((void**)&d2L, g_d2L);
    cudaGetSymbolAddress((void**)&fpH, g_fpH);   cudaGetSymbolAddress((void**)&fpL, g_fpL);
    cudaGetSymbolAddress((void**)&rgH, g_rgbTH); cudaGetSymbolAddress((void**)&rgL, g_rgbTL);
    cudaGetSymbolAddress((void**)&fpF, g_fpF);   cudaGetSymbolAddress((void**)&s1F, g_s1F);
    cudaGetSymbolAddress((void**)&whi, g_whi);   cudaGetSymbolAddress((void**)&wlo, g_wlo);
    cudaGetSymbolAddress((void**)&idx, g_idx);

    float* out = (float*)d_out;

    const int SMEM = 2 * STG * 2;   // 81920 bytes
    cudaFuncSetAttribute(gemm_hmma, cudaFuncAttributeMaxDynamicSharedMemorySize, SMEM);

    const int O_CC1 = 0,      O_CC2 = 147456, O_CO1 = 196608, O_CO2 = 262144;
    const int O_DH1 = 294912, O_DH2 = 325632, O_DH3 = 356352, O_SH1 = 380928;

    // order chosen so cc1 is the 4th launch (ncu -s 5 -c 1 captures it)
    prep_misc<<<PREP_BLKS + 1024, dim3(32, 8)>>>(cc1_w, cc2_w, co1_w, co2_w,
                                                 dh1_w, dh2_w, dh3_w, sh1_w, whi, wlo,
                                                 rgb_feat, rgH, rgL);
    knn_kernel<<<NP / 128, 256>>>(pcd_xyz, rgb_xyz, idx);
    gather_kernel<<<NP * 3 * 32 / 256, 256>>>(rgH, rgL, idx, xcH, xcL);

    gemm_hmma<<<dim3(128, 3), 256, SMEM>>>(xcH, xcL, 384, 384, whi + O_CC1, wlo + O_CC1, 384, 384,
                                           h1H, h1L, 384, nullptr, 0, cc1_b, cc_bn, 1);

    maxfeat_kernel<<<NP * 32 / 256, 256>>>(rgH, rgL, idx, b2H, b2L);
    tpose_pcd<<<NP / 32, dim3(32, 8)>>>(pcd_feat, fuH, fuL);

    gemm_hmma<<<dim3(128, 1), 256, SMEM>>>(h1H, h1L, 384, 384, whi + O_CC2, wlo + O_CC2, 384, 128,
                                           b2H, b2L, 256, nullptr, 0, cc2_b, nullptr, 0);
    gemm_hmma<<<dim3(128, 2), 256, SMEM>>>(b2H, b2L, 256, 256, whi + O_CO1, wlo + O_CO1, 256, 256,
                                           coH, coL, 256, nullptr, 0, co1_b, co_bn, 1);
    gemm_hmma<<<dim3(128, 1), 256, SMEM>>>(coH, coL, 256, 256, whi + O_CO2, wlo + O_CO2, 256, 128,
                                           fuH + 32, fuL + 32, 160, nullptr, 0, co2_b, nullptr, 0);
    gemm_hmma<<<dim3(128, 2), 256, SMEM>>>(fuH, fuL, 160, 160, whi + O_DH1, wlo + O_DH1, 192, 160,
                                           d1H, d1L, 160, nullptr, 0, dh1_b, dh1_bn, 1);
    gemm_hmma<<<dim3(128, 2), 256, SMEM>>>(d1H, d1L, 160, 160, whi + O_DH2, wlo + O_DH2, 192, 160,
                                           d2H, d2L, 160, nullptr, 0, dh2_b, dh2_bn, 1);
    gemm_hmma<<<dim3(128, 1), 256, SMEM>>>(d2H, d2L, 160, 160, whi + O_DH3, wlo + O_DH3, 192, 128,
                                           fpH, fpL, 128, fpF, 128, dh3_b, nullptr, 0);
    gemm_hmma<<<dim3(128, 1), 256, SMEM>>>(fpH, fpL, 128, 128, whi + O_SH1, wlo + O_SH1, 128, 128,
                                           nullptr, nullptr, 0, s1F, 128, sh1_b, sh_bn, 1);

    // outputs: [pcd_xyz (NP*3)] [vote_scores (NP)] [vf (NP,128)]
    score_kernel<<<NP / 8, 256>>>(s1F, sh2_w, sh2_b, out + NP * 3);
    normalize_kernel<<<NP / 8, 256>>>(fpF, out + NP * 3 + NP);
    cudaMemcpyAsync(out, pcd_xyz, NP * 3 * sizeof(float), cudaMemcpyDeviceToDevice, 0);
}

// round 14
// speedup vs baseline: 1.0851x; 1.0851x over previous
#include <cuda_runtime.h>
#include <cuda_fp16.h>
#include <math.h>

#define NP 16384
#define NR 8192

typedef unsigned long long ull;

// ============================ scratch buffers ============================
__device__ __align__(16) __half g_xcatH[(size_t)NP * 384];
__device__ __align__(16) __half g_xcatL[(size_t)NP * 384];
__device__ __align__(16) __half g_h1H  [(size_t)NP * 384];
__device__ __align__(16) __half g_h1L  [(size_t)NP * 384];
__device__ __align__(16) __half g_buf2H[(size_t)NP * 256];   // cols 0-127 cc2, 128-255 maxfeat
__device__ __align__(16) __half g_buf2L[(size_t)NP * 256];
__device__ __align__(16) __half g_co1H [(size_t)NP * 256];
__device__ __align__(16) __half g_co1L [(size_t)NP * 256];
__device__ __align__(16) __half g_fullH[(size_t)NP * 160];   // cols 0-31 pcd, 32-159 attach
__device__ __align__(16) __half g_fullL[(size_t)NP * 160];
__device__ __align__(16) __half g_d1H  [(size_t)NP * 160];
__device__ __align__(16) __half g_d1L  [(size_t)NP * 160];
__device__ __align__(16) __half g_d2H  [(size_t)NP * 160];
__device__ __align__(16) __half g_d2L  [(size_t)NP * 160];
__device__ __align__(16) __half g_fpH  [(size_t)NP * 128];
__device__ __align__(16) __half g_fpL  [(size_t)NP * 128];
__device__ __align__(16) float  g_fpF  [(size_t)NP * 128];
__device__ __align__(16) float  g_s1F  [(size_t)NP * 128];
__device__ __align__(16) __half g_rgbTH[(size_t)NR * 128];
__device__ __align__(16) __half g_rgbTL[(size_t)NR * 128];
__device__ int g_idx[NP * 3];
#define WTOT 397312
__device__ __align__(16) __half g_whi[WTOT];
__device__ __align__(16) __half g_wlo[WTOT];

// ============================ helpers ============================
__device__ __forceinline__ void splitf(float x, __half& h, __half& l) {
    h = __float2half(x);
    l = __float2half(x - __half2float(h));
}
__device__ __forceinline__ void mma16816(float* d, const unsigned* a, const unsigned* b) {
    asm volatile("mma.sync.aligned.m16n8k16.row.col.f32.f16.f16.f32 "
        "{%0,%1,%2,%3}, {%4,%5,%6,%7}, {%8,%9}, {%0,%1,%2,%3};"
        : "+f"(d[0]), "+f"(d[1]), "+f"(d[2]), "+f"(d[3])
        : "r"(a[0]), "r"(a[1]), "r"(a[2]), "r"(a[3]), "r"(b[0]), "r"(b[1]));
}
// fp16-accumulate variant: corrections only (values ~2^-11 of main term)
__device__ __forceinline__ void mma16816h(unsigned* d, const unsigned* a, const unsigned* b) {
    asm volatile("mma.sync.aligned.m16n8k16.row.col.f16.f16.f16.f16 "
        "{%0,%1}, {%2,%3,%4,%5}, {%6,%7}, {%0,%1};"
        : "+r"(d[0]), "+r"(d[1])
        : "r"(a[0]), "r"(a[1]), "r"(a[2]), "r"(a[3]), "r"(b[0]), "r"(b[1]));
}
__device__ __forceinline__ void ldm4(unsigned* r, unsigned addr) {
    asm volatile("ldmatrix.sync.aligned.m8n8.x4.shared.b16 {%0,%1,%2,%3}, [%4];"
        : "=r"(r[0]), "=r"(r[1]), "=r"(r[2]), "=r"(r[3]) : "r"(addr));
}
__device__ __forceinline__ void cpa16(unsigned dst, const void* src) {
    asm volatile("cp.async.cg.shared.global [%0], [%1], 16;" :: "r"(dst), "l"(src));
}
__device__ __forceinline__ void cpa_commit() {
    asm volatile("cp.async.commit_group;" ::: "memory");
}
__device__ __forceinline__ void cpa_wait0() {
    asm volatile("cp.async.wait_group 0;" ::: "memory");
}

// ============================ fused prep: weight split + rgb transpose ============================
#define PREP_BLKS ((WTOT + 255) / 256)
__global__ void prep_misc(
    const float* __restrict__ cc1, const float* __restrict__ cc2,
    const float* __restrict__ co1, const float* __restrict__ co2,
    const float* __restrict__ dh1, const float* __restrict__ dh2,
    const float* __restrict__ dh3, const float* __restrict__ sh1,
    __half* __restrict__ dhi, __half* __restrict__ dlo,
    const float* __restrict__ rgbf,
    __half* __restrict__ rgbTH, __half* __restrict__ rgbTL)
{
    int bid = blockIdx.x;
    if (bid < PREP_BLKS) {
        int g = bid * 256 + threadIdx.y * 32 + threadIdx.x;
        if (g >= WTOT) return;
        const float* src; int loc, K, Kpad;
        if      (g < 147456) { src = cc1; loc = g;          K = 384; Kpad = 384; }
        else if (g < 196608) { src = cc2; loc = g - 147456; K = 384; Kpad = 384; }
        else if (g < 262144) { src = co1; loc = g - 196608; K = 256; Kpad = 256; }
        else if (g < 294912) { src = co2; loc = g - 262144; K = 256; Kpad = 256; }
        else if (g < 325632) { src = dh1; loc = g - 294912; K = 160; Kpad = 192; }
        else if (g < 356352) { src = dh2; loc = g - 325632; K = 160; Kpad = 192; }
        else if (g < 380928) { src = dh3; loc = g - 356352; K = 160; Kpad = 192; }
        else                 { src = sh1; loc = g - 380928; K = 128; Kpad = 128; }
        int r = loc / Kpad, c = loc - r * Kpad;
        float x = (c < K) ? src[r * K + c] : 0.f;
        __half h, l; splitf(x, h, l);
        dhi[g] = h; dlo[g] = l;
    } else {
        __shared__ float tile[32][33];
        int b2 = bid - PREP_BLKS;
        int c0 = (b2 >> 8) * 32;
        int n0 = (b2 & 255) * 32;
        #pragma unroll
        for (int i = 0; i < 32; i += 8)
            tile[threadIdx.y + i][threadIdx.x] = rgbf[(c0 + threadIdx.y + i) * NR + n0 + threadIdx.x];
        __syncthreads();
        #pragma unroll
        for (int i = 0; i < 32; i += 8) {
            float v = tile[threadIdx.x][threadIdx.y + i];
            __half h, l; splitf(v, h, l);
            size_t o = (size_t)(n0 + threadIdx.y + i) * 128 + c0 + threadIdx.x;
            rgbTH[o] = h; rgbTL[o] = l;
        }
    }
}

// ============================ 3-NN: 256 blocks, 4 threads/point ============================
__global__ __launch_bounds__(256) void knn_kernel(const float* __restrict__ pcd,
                                                  const float* __restrict__ rgb,
                                                  int* __restrict__ outIdx)
{
    __shared__ float4 srgb[2048];
    __shared__ float  md[256 * 3];
    __shared__ int    mi[256 * 3];
    int tid = threadIdx.x;
    int pl  = tid & 63;                 // point lane
    int q   = tid >> 6;                 // quadrant 0..3 (indices == q mod 4)
    int p   = blockIdx.x * 64 + pl;
    float px = pcd[p * 3 + 0], py = pcd[p * 3 + 1], pz = pcd[p * 3 + 2];
    float b0 = 1e30f, b1 = 1e30f, b2 = 1e30f;
    int i0 = 0, i1 = 0, i2 = 0;
    for (int t = 0; t < NR; t += 2048) {
        __syncthreads();
        for (int e = tid; e < 2048; e += 256) {
            int j = t + e;
            srgb[e] = make_float4(rgb[j * 3 + 0], rgb[j * 3 + 1], rgb[j * 3 + 2], 0.f);
        }
        __syncthreads();
        #pragma unroll 8
        for (int i = 0; i < 512; i++) {
            int e = (i << 2) | q;
            float4 rr = srgb[e];
            float dx = px - rr.x, dy = py - rr.y, dz = pz - rr.z;
            float d2 = dx * dx; d2 = fmaf(dy, dy, d2); d2 = fmaf(dz, dz, d2);
            if (d2 < b2) {
                int idx = t + e;
                if (d2 < b0)      { b2 = b1; i2 = i1; b1 = b0; i1 = i0; b0 = d2; i0 = idx; }
                else if (d2 < b1) { b2 = b1; i2 = i1; b1 = d2; i1 = idx; }
                else              { b2 = d2; i2 = idx; }
            }
        }
    }
    md[tid * 3 + 0] = b0; md[tid * 3 + 1] = b1; md[tid * 3 + 2] = b2;
    mi[tid * 3 + 0] = i0; mi[tid * 3 + 1] = i1; mi[tid * 3 + 2] = i2;
    __syncthreads();
    if (tid < 64) {
        // 4-way merge over quadrant lists (rows tid, tid+64, tid+128, tid+192),
        // ordered by (d2, idx) to match top_k's stable lower-index-first rule.
        int ptr[4] = {0, 0, 0, 0};
        #pragma unroll
        for (int t3 = 0; t3 < 3; t3++) {
            float best = 3.4e38f; int bq = 0, bidx = 0x7fffffff;
            #pragma unroll
            for (int qq = 0; qq < 4; qq++) {
                if (ptr[qq] < 3) {
                    int rr = (qq * 64 + tid) * 3 + ptr[qq];
                    float d = md[rr]; int ix = mi[rr];
                    if (d < best || (d == best && ix < bidx)) { best = d; bq = qq; bidx = ix; }
                }
            }
            ptr[bq]++;
            outIdx[p * 3 + t3] = (sqrtf(best) > 0.075f) ? -1 : bidx;
        }
    }
}

// ============================ staging kernels ============================
__global__ void tpose_pcd(const float* __restrict__ in,
                          __half* __restrict__ outH, __half* __restrict__ outL)
{
    __shared__ float t[32][33];
    int n0 = blockIdx.x * 32;
    int tx = threadIdx.x, ty = threadIdx.y;
    #pragma unroll
    for (int i = 0; i < 32; i += 8) t[ty + i][tx] = in[(ty + i) * NP + n0 + tx];
    __syncthreads();
    #pragma unroll
    for (int i = 0; i < 32; i += 8) {
        float v = t[tx][ty + i];
        __half h, l; splitf(v, h, l);
        size_t o = (size_t)(n0 + ty + i) * 160 + tx;
        outH[o] = h; outL[o] = l;
    }
}

__global__ __launch_bounds__(256) void gather_kernel(
    const __half* __restrict__ rgbTH, const __half* __restrict__ rgbTL,
    const int* __restrict__ idx,
    __half* __restrict__ xcatH, __half* __restrict__ xcatL)
{
    int e = blockIdx.x * 256 + threadIdx.x;
    int c4 = e & 31;
    int t = e >> 5;
    int p = t / 3, j = t - p * 3;
    int row = idx[p * 3 + j];
    uint2 vh = make_uint2(0u, 0u), vl = make_uint2(0u, 0u);
    if (row >= 0) {
        vh = *(const uint2*)(rgbTH + (size_t)row * 128 + c4 * 4);
        vl = *(const uint2*)(rgbTL + (size_t)row * 128 + c4 * 4);
    }
    size_t o = (size_t)p * 384 + j * 128 + c4 * 4;
    *(uint2*)(xcatH + o) = vh;
    *(uint2*)(xcatL + o) = vl;
}

__global__ __launch_bounds__(256) void maxfeat_kernel(
    const __half* __restrict__ rgbTH, const __half* __restrict__ rgbTL,
    const int* __restrict__ idx,
    __half* __restrict__ buf2H, __half* __restrict__ buf2L)
{
    int e = blockIdx.x * 256 + threadIdx.x;
    int c4 = e & 31;
    int p = e >> 5;
    float m[4] = {-1e30f, -1e30f, -1e30f, -1e30f};
    #pragma unroll
    for (int j = 0; j < 3; j++) {
        int row = idx[p * 3 + j];
        float v[4] = {0.f, 0.f, 0.f, 0.f};
        if (row >= 0) {
            const __half* ph = rgbTH + (size_t)row * 128 + c4 * 4;
            const __half* pl = rgbTL + (size_t)row * 128 + c4 * 4;
            #pragma unroll
            for (int q = 0; q < 4; q++)
                v[q] = __half2float(ph[q]) + __half2float(pl[q]);
        }
        #pragma unroll
        for (int q = 0; q < 4; q++) m[q] = fmaxf(m[q], v[q]);
    }
    __half hh[4], ll[4];
    #pragma unroll
    for (int q = 0; q < 4; q++) splitf(m[q], hh[q], ll[q]);
    size_t o = (size_t)p * 256 + 128 + c4 * 4;
    *(__half2*)(buf2H + o)     = __halves2half2(hh[0], hh[1]);
    *(__half2*)(buf2H + o + 2) = __halves2half2(hh[2], hh[3]);
    *(__half2*)(buf2L + o)     = __halves2half2(ll[0], ll[1]);
    *(__half2*)(buf2L + o + 2) = __halves2half2(ll[2], ll[3]);
}

// ============================ HMMA GEMM (128x128, cp.async, ldmatrix, f16-acc corrections) ============================
// Y[p, m] = sum_k X[p,k] * W[m,k]; X/W fp16 hi/lo planes.
// main term XhWh accumulated fp32; corrections XlWh + XhWl accumulated fp16 (values ~2^-11 of main).
#define LDW 40
#define PLANE (128 * LDW)
#define STG   (4 * PLANE)
#define AH 0
#define AL PLANE
#define BH (2 * PLANE)
#define BL (3 * PLANE)
__global__ __launch_bounds__(256, 2) void gemm_hmma(
    const __half* __restrict__ Xh, const __half* __restrict__ Xl, int pitchA, int K,
    const __half* __restrict__ Whi, const __half* __restrict__ Wlo, int Wpitch, int Cout,
    __half* __restrict__ Yh, __half* __restrict__ Yl, int pitchY,
    float* __restrict__ Yf, int pitchYf,
    const float* __restrict__ bias, const float* __restrict__ bn, int mode)
{
    extern __shared__ __half sdyn[];
    __shared__ float sSc[128], sSh[128];

    const int tid = threadIdx.x;
    const int lane = tid & 31, wid = tid >> 5;
    const int wm = wid >> 1, wn = wid & 1;
    const int g = lane >> 2, tc = lane & 3;
    const int n0 = blockIdx.x * 128;
    const int nb0 = blockIdx.y * 128;
    const int NT = min(128, Cout - nb0);

    if (tid < 128) {
        float sc = 0.f, sh = 0.f;
        if (tid < NT) {
            int m = nb0 + tid;
            float b = bias[m];
            sc = 1.f; sh = b;
            if (mode) {
                float gg = bn[m], be = bn[Cout + m], mn = bn[2 * Cout + m], v = bn[3 * Cout + m];
                float inv = gg * rsqrtf(v + 1e-5f);
                sc = inv; sh = (b - mn) * inv + be;
            }
        }
        sSc[tid] = sc; sSh[tid] = sh;
    }

    float macc[2][8][4];
    unsigned cacc[2][8][2];
    #pragma unroll
    for (int a = 0; a < 2; a++)
        #pragma unroll
        for (int b = 0; b < 8; b++) {
            #pragma unroll
            for (int c = 0; c < 4; c++) macc[a][b][c] = 0.f;
            cacc[a][b][0] = 0u; cacc[a][b][1] = 0u;
        }

    const int r0c = tid >> 2,         o0c = (tid & 3) * 8;
    const int r1c = (tid + 256) >> 2, o1c = ((tid + 256) & 3) * 8;
    const unsigned sbase = (unsigned)__cvta_generic_to_shared(sdyn);

    const int slabs = K >> 5;

    #define LOAD_SLAB(sl) do {                                                      \
        int k0_ = (sl) << 5;                                                        \
        unsigned sb_ = sbase + ((sl) & 1) * (STG * 2);                              \
        cpa16(sb_ + (AH + r0c * LDW + o0c) * 2, Xh + (size_t)(n0 + r0c) * pitchA + k0_ + o0c);  \
        cpa16(sb_ + (AH + r1c * LDW + o1c) * 2, Xh + (size_t)(n0 + r1c) * pitchA + k0_ + o1c);  \
        cpa16(sb_ + (AL + r0c * LDW + o0c) * 2, Xl + (size_t)(n0 + r0c) * pitchA + k0_ + o0c);  \
        cpa16(sb_ + (AL + r1c * LDW + o1c) * 2, Xl + (size_t)(n0 + r1c) * pitchA + k0_ + o1c);  \
        cpa16(sb_ + (BH + r0c * LDW + o0c) * 2, Whi + (size_t)(nb0 + r0c) * Wpitch + k0_ + o0c); \
        cpa16(sb_ + (BH + r1c * LDW + o1c) * 2, Whi + (size_t)(nb0 + r1c) * Wpitch + k0_ + o1c); \
        cpa16(sb_ + (BL + r0c * LDW + o0c) * 2, Wlo + (size_t)(nb0 + r0c) * Wpitch + k0_ + o0c); \
        cpa16(sb_ + (BL + r1c * LDW + o1c) * 2, Wlo + (size_t)(nb0 + r1c) * Wpitch + k0_ + o1c); \
        cpa_commit();                                                               \
    } while (0)

    const int arow = wm * 32 + (lane & 15);
    const int akk0 = (lane >> 4) * 8;
    const int brow = wn * 64 + ((lane >> 4) << 3) + (lane & 7);
    const int bkk0 = ((lane >> 3) & 1) * 8;

    LOAD_SLAB(0);
    for (int sl = 0; sl < slabs; sl++) {
        cpa_wait0();
        __syncthreads();
        if (sl + 1 < slabs) LOAD_SLAB(sl + 1);

        const unsigned stb = sbase + (sl & 1) * (STG * 2);
        #pragma unroll
        for (int s = 0; s < 2; s++) {
            const int akk = s * 16 + akk0;
            const int bkk = s * 16 + bkk0;
            unsigned ah[2][4], al[2][4];
            #pragma unroll
            for (int mt = 0; mt < 2; mt++) {
                unsigned off = ((arow + mt * 16) * LDW + akk) * 2;
                ldm4(ah[mt], stb + (AH * 2) + off);
                ldm4(al[mt], stb + (AL * 2) + off);
            }
            #pragma unroll
            for (int jp = 0; jp < 4; jp++) {
                unsigned boff = ((brow + jp * 16) * LDW + bkk) * 2;
                unsigned bh[4], bl[4];
                ldm4(bh, stb + (BH * 2) + boff);
                ldm4(bl, stb + (BL * 2) + boff);
                #pragma unroll
                for (int h = 0; h < 2; h++) {
                    int nt = jp * 2 + h;
                    #pragma unroll
                    for (int mt = 0; mt < 2; mt++) {
                        mma16816(macc[mt][nt], ah[mt], bh + 2 * h);
                        mma16816h(cacc[mt][nt], al[mt], bh + 2 * h);
                        mma16816h(cacc[mt][nt], ah[mt], bl + 2 * h);
                    }
                }
            }
        }
        __syncthreads();
    }

    // --- epilogue: main + corrections, BN/ReLU, emit planes ---
    #pragma unroll
    for (int mt = 0; mt < 2; mt++) {
        int r0 = n0 + wm * 32 + mt * 16 + g;
        #pragma unroll
        for (int nt = 0; nt < 8; nt++) {
            int col = wn * 64 + nt * 8 + tc * 2;
            if (col < NT) {
                float sc0 = sSc[col], sh0 = sSh[col];
                float sc1 = sSc[col + 1], sh1 = sSh[col + 1];
                float* a = macc[mt][nt];
                __half2 c01 = *(__half2*)&cacc[mt][nt][0];
                __half2 c23 = *(__half2*)&cacc[mt][nt][1];
                float y0 = (a[0] + __low2float(c01))  * sc0 + sh0;
                float y1 = (a[1] + __high2float(c01)) * sc1 + sh1;
                float y2 = (a[2] + __low2float(c23))  * sc0 + sh0;
                float y3 = (a[3] + __high2float(c23)) * sc1 + sh1;
                if (mode) {
                    y0 = fmaxf(y0, 0.f); y1 = fmaxf(y1, 0.f);
                    y2 = fmaxf(y2, 0.f); y3 = fmaxf(y3, 0.f);
                }
                if (Yf) {
                    *(float2*)(Yf + (size_t)r0 * pitchYf + nb0 + col)       = make_float2(y0, y1);
                    *(float2*)(Yf + (size_t)(r0 + 8) * pitchYf + nb0 + col) = make_float2(y2, y3);
                }
                if (Yh) {
                    __half h0, l0, h1, l1, h2, l2, h3, l3;
                    splitf(y0, h0, l0); splitf(y1, h1, l1);
                    splitf(y2, h2, l2); splitf(y3, h3, l3);
                    *(__half2*)(Yh + (size_t)r0 * pitchY + nb0 + col)       = __halves2half2(h0, h1);
                    *(__half2*)(Yh + (size_t)(r0 + 8) * pitchY + nb0 + col) = __halves2half2(h2, h3);
                    *(__half2*)(Yl + (size_t)r0 * pitchY + nb0 + col)       = __halves2half2(l0, l1);
                    *(__half2*)(Yl + (size_t)(r0 + 8) * pitchY + nb0 + col) = __halves2half2(l2, l3);
                }
            }
        }
    }
}

// ============================ heads ============================
__global__ __launch_bounds__(256) void score_kernel(const float* __restrict__ s,
                                                    const float* __restrict__ w,
                                                    const float* __restrict__ b,
                                                    float* __restrict__ out)
{
    int wid = threadIdx.x >> 5, lid = threadIdx.x & 31;
    int p = blockIdx.x * 8 + wid;
    float4 v = *(const float4*)(s + (size_t)p * 128 + lid * 4);
    float4 ww = *(const float4*)(w + lid * 4);
    float sum = v.x * ww.x + v.y * ww.y + v.z * ww.z + v.w * ww.w;
    #pragma unroll
    for (int o = 16; o > 0; o >>= 1) sum += __shfl_xor_sync(0xffffffff, sum, o);
    if (lid == 0) out[p] = 1.f / (1.f + expf(-(sum + b[0])));
}

__global__ __launch_bounds__(256) void normalize_kernel(const float* __restrict__ fp,
                                                        float* __restrict__ out)
{
    int wid = threadIdx.x >> 5, lid = threadIdx.x & 31;
    int p = blockIdx.x * 8 + wid;
    float4 v = *(const float4*)(fp + (size_t)p * 128 + lid * 4);
    float ss = v.x * v.x + v.y * v.y + v.z * v.z + v.w * v.w;
    #pragma unroll
    for (int o = 16; o > 0; o >>= 1) ss += __shfl_xor_sync(0xffffffff, ss, o);
    float inv = 1.f / fmaxf(sqrtf(ss), 1e-12f);
    float4 r = make_float4(v.x * inv, v.y * inv, v.z * inv, v.w * inv);
    *(float4*)(out + (size_t)p * 128 + lid * 4) = r;
}

// ============================ launch ============================
extern "C" void kernel_launch(void* const* d_in, const int* in_sizes, int n_in,
                              void* d_out, int out_size)
{
    const float* pcd_xyz  = (const float*)d_in[0];
    const float* rgb_xyz  = (const float*)d_in[1];
    const float* pcd_feat = (const float*)d_in[2];
    const float* rgb_feat = (const float*)d_in[3];
    const float* cc1_w = (const float*)d_in[4];
    const float* cc1_b = (const float*)d_in[5];
    const float* cc_bn = (const float*)d_in[6];
    const float* cc2_w = (const float*)d_in[7];
    const float* cc2_b = (const float*)d_in[8];
    const float* co1_w = (const float*)d_in[9];
    const float* co1_b = (const float*)d_in[10];
    const float* co_bn = (const float*)d_in[11];
    const float* co2_w = (const float*)d_in[12];
    const float* co2_b = (const float*)d_in[13];
    const float* dh1_w = (const float*)d_in[14];
    const float* dh1_b = (const float*)d_in[15];
    const float* dh1_bn = (const float*)d_in[16];
    const float* dh2_w = (const float*)d_in[17];
    const float* dh2_b = (const float*)d_in[18];
    const float* dh2_bn = (const float*)d_in[19];
    const float* dh3_w = (const float*)d_in[20];
    const float* dh3_b = (const float*)d_in[21];
    const float* sh1_w = (const float*)d_in[22];
    const float* sh1_b = (const float*)d_in[23];
    const float* sh_bn = (const float*)d_in[24];
    const float* sh2_w = (const float*)d_in[25];
    const float* sh2_b = (const float*)d_in[26];

    __half *xcH, *xcL, *h1H, *h1L, *b2H, *b2L, *coH, *coL, *fuH, *fuL;
    __half *d1H, *d1L, *d2H, *d2L, *fpH, *fpL, *rgH, *rgL, *whi, *wlo;
    float *fpF, *s1F;
    int* idx;
    cudaGetSymbolAddress((void**)&xcH, g_xcatH); cudaGetSymbolAddress((void**)&xcL, g_xcatL);
    cudaGetSymbolAddress((void**)&h1H, g_h1H);   cudaGetSymbolAddress((void**)&h1L, g_h1L);
    cudaGetSymbolAddress((void**)&b2H, g_buf2H); cudaGetSymbolAddress((void**)&b2L, g_buf2L);
    cudaGetSymbolAddress((void**)&coH, g_co1H);  cudaGetSymbolAddress((void**)&coL, g_co1L);
    cudaGetSymbolAddress((void**)&fuH, g_fullH); cudaGetSymbolAddress((void**)&fuL, g_fullL);
    cudaGetSymbolAddress((void**)&d1H, g_d1H);   cudaGetSymbolAddress((void**)&d1L, g_d1L);
    cudaGetSymbolAddress((void**)&d2H, g_d2H);   cudaGetSymbolAddress((void**)&d2L, g_d2L);
    cudaGetSymbolAddress((void**)&fpH, g_fpH);   cudaGetSymbolAddress((void**)&fpL, g_fpL);
    cudaGetSymbolAddress((void**)&rgH, g_rgbTH); cudaGetSymbolAddress((void**)&rgL, g_rgbTL);
    cudaGetSymbolAddress((void**)&fpF, g_fpF);   cudaGetSymbolAddress((void**)&s1F, g_s1F);
    cudaGetSymbolAddress((void**)&whi, g_whi);   cudaGetSymbolAddress((void**)&wlo, g_wlo);
    cudaGetSymbolAddress((void**)&idx, g_idx);

    float* out = (float*)d_out;

    const int SMEM = 2 * STG * 2;   // 81920 bytes
    cudaFuncSetAttribute(gemm_hmma, cudaFuncAttributeMaxDynamicSharedMemorySize, SMEM);

    const int O_CC1 = 0,      O_CC2 = 147456, O_CO1 = 196608, O_CO2 = 262144;
    const int O_DH1 = 294912, O_DH2 = 325632, O_DH3 = 356352, O_SH1 = 380928;

    // order chosen so cc1 is the 4th launch (ncu -s 5 -c 1 captures it)
    prep_misc<<<PREP_BLKS + 1024, dim3(32, 8)>>>(cc1_w, cc2_w, co1_w, co2_w,
                                                 dh1_w, dh2_w, dh3_w, sh1_w, whi, wlo,
                                                 rgb_feat, rgH, rgL);
    knn_kernel<<<NP / 64, 256>>>(pcd_xyz, rgb_xyz, idx);
    gather_kernel<<<NP * 3 * 32 / 256, 256>>>(rgH, rgL, idx, xcH, xcL);

    gemm_hmma<<<dim3(128, 3), 256, SMEM>>>(xcH, xcL, 384, 384, whi + O_CC1, wlo + O_CC1, 384, 384,
                                           h1H, h1L, 384, nullptr, 0, cc1_b, cc_bn, 1);

    maxfeat_kernel<<<NP * 32 / 256, 256>>>(rgH, rgL, idx, b2H, b2L);
    tpose_pcd<<<NP / 32, dim3(32, 8)>>>(pcd_feat, fuH, fuL);

    gemm_hmma<<<dim3(128, 1), 256, SMEM>>>(h1H, h1L, 384, 384, whi + O_CC2, wlo + O_CC2, 384, 128,
                                           b2H, b2L, 256, nullptr, 0, cc2_b, nullptr, 0);
    gemm_hmma<<<dim3(128, 2), 256, SMEM>>>(b2H, b2L, 256, 256, whi + O_CO1, wlo + O_CO1, 256, 256,
                                           coH, coL, 256, nullptr, 0, co1_b, co_bn, 1);
    gemm_hmma<<<dim3(128, 1), 256, SMEM>>>(coH, coL, 256, 256, whi + O_CO2, wlo + O_CO2, 256, 128,
                                           fuH + 32, fuL + 32, 160, nullptr, 0, co2_b, nullptr, 0);
    gemm_hmma<<<dim3(128, 2), 256, SMEM>>>(fuH, fuL, 160, 160, whi + O_DH1, wlo + O_DH1, 192, 160,
                                           d1H, d1L, 160, nullptr, 0, dh1_b, dh1_bn, 1);
    gemm_hmma<<<dim3(128, 2), 256, SMEM>>>(d1H, d1L, 160, 160, whi + O_DH2, wlo + O_DH2, 192, 160,
                                           d2H, d2L, 160, nullptr, 0, dh2_b, dh2_bn, 1);
    gemm_hmma<<<dim3(128, 1), 256, SMEM>>>(d2H, d2L, 160, 160, whi + O_DH3, wlo + O_DH3, 192, 128,
                                           fpH, fpL, 128, fpF, 128, dh3_b, nullptr, 0);
    gemm_hmma<<<dim3(128, 1), 256, SMEM>>>(fpH, fpL, 128, 128, whi + O_SH1, wlo + O_SH1, 128, 128,
                                           nullptr, nullptr, 0, s1F, 128, sh1_b, sh_bn, 1);

    // outputs: [pcd_xyz (NP*3)] [vote_scores (NP)] [vf (NP,128)]
    score_kernel<<<NP / 8, 256>>>(s1F, sh2_w, sh2_b, out + NP * 3);
    normalize_kernel<<<NP / 8, 256>>>(fpF, out + NP * 3 + NP);
    cudaMemcpyAsync(out, pcd_xyz, NP * 3 * sizeof(float), cudaMemcpyDeviceToDevice, 0);
}

// round 15
// speedup vs baseline: 1.1145x; 1.0271x over previous
#include <cuda_runtime.h>
#include <cuda_fp16.h>
#include <math.h>

#define NP 16384
#define NR 8192

typedef unsigned long long ull;

// ============================ scratch buffers ============================
__device__ __align__(16) __half g_xcatH[(size_t)NP * 384];
__device__ __align__(16) __half g_xcatL[(size_t)NP * 384];
__device__ __align__(16) __half g_h1H  [(size_t)NP * 384];
__device__ __align__(16) __half g_h1L  [(size_t)NP * 384];
__device__ __align__(16) __half g_buf2H[(size_t)NP * 256];   // cols 0-127 cc2, 128-255 maxfeat
__device__ __align__(16) __half g_buf2L[(size_t)NP * 256];
__device__ __align__(16) __half g_co1H [(size_t)NP * 256];
__device__ __align__(16) __half g_co1L [(size_t)NP * 256];
__device__ __align__(16) __half g_fullH[(size_t)NP * 160];   // cols 0-31 pcd, 32-159 attach
__device__ __align__(16) __half g_fullL[(size_t)NP * 160];
__device__ __align__(16) __half g_d1H  [(size_t)NP * 160];
__device__ __align__(16) __half g_d1L  [(size_t)NP * 160];
__device__ __align__(16) __half g_d2H  [(size_t)NP * 160];
__device__ __align__(16) __half g_d2L  [(size_t)NP * 160];
__device__ __align__(16) __half g_fpH  [(size_t)NP * 128];
__device__ __align__(16) __half g_fpL  [(size_t)NP * 128];
__device__ __align__(16) float  g_fpF  [(size_t)NP * 128];
__device__ __align__(16) float  g_s1F  [(size_t)NP * 128];
__device__ __align__(16) __half g_rgbTH[(size_t)NR * 128];
__device__ __align__(16) __half g_rgbTL[(size_t)NR * 128];
__device__ int g_idx[NP * 3];
#define WTOT 397312
__device__ __align__(16) __half g_whi[WTOT];
__device__ __align__(16) __half g_wlo[WTOT];

// ============================ helpers ============================
__device__ __forceinline__ void splitf(float x, __half& h, __half& l) {
    h = __float2half(x);
    l = __float2half(x - __half2float(h));
}
__device__ __forceinline__ void mma16816(float* d, const unsigned* a, const unsigned* b) {
    asm volatile("mma.sync.aligned.m16n8k16.row.col.f32.f16.f16.f32 "
        "{%0,%1,%2,%3}, {%4,%5,%6,%7}, {%8,%9}, {%0,%1,%2,%3};"
        : "+f"(d[0]), "+f"(d[1]), "+f"(d[2]), "+f"(d[3])
        : "r"(a[0]), "r"(a[1]), "r"(a[2]), "r"(a[3]), "r"(b[0]), "r"(b[1]));
}
__device__ __forceinline__ void ldm4(unsigned* r, unsigned addr) {
    asm volatile("ldmatrix.sync.aligned.m8n8.x4.shared.b16 {%0,%1,%2,%3}, [%4];"
        : "=r"(r[0]), "=r"(r[1]), "=r"(r[2]), "=r"(r[3]) : "r"(addr));
}
__device__ __forceinline__ void cpa16(unsigned dst, const void* src) {
    asm volatile("cp.async.cg.shared.global [%0], [%1], 16;" :: "r"(dst), "l"(src));
}
__device__ __forceinline__ void cpa_commit() {
    asm volatile("cp.async.commit_group;" ::: "memory");
}
__device__ __forceinline__ void cpa_wait0() {
    asm volatile("cp.async.wait_group 0;" ::: "memory");
}

// ============================ fused prep: weight split + rgb transpose ============================
#define PREP_BLKS ((WTOT + 255) / 256)
__global__ void prep_misc(
    const float* __restrict__ cc1, const float* __restrict__ cc2,
    const float* __restrict__ co1, const float* __restrict__ co2,
    const float* __restrict__ dh1, const float* __restrict__ dh2,
    const float* __restrict__ dh3, const float* __restrict__ sh1,
    __half* __restrict__ dhi, __half* __restrict__ dlo,
    const float* __restrict__ rgbf,
    __half* __restrict__ rgbTH, __half* __restrict__ rgbTL)
{
    int bid = blockIdx.x;
    if (bid < PREP_BLKS) {
        int g = bid * 256 + threadIdx.y * 32 + threadIdx.x;
        if (g >= WTOT) return;
        const float* src; int loc, K, Kpad;
        if      (g < 147456) { src = cc1; loc = g;          K = 384; Kpad = 384; }
        else if (g < 196608) { src = cc2; loc = g - 147456; K = 384; Kpad = 384; }
        else if (g < 262144) { src = co1; loc = g - 196608; K = 256; Kpad = 256; }
        else if (g < 294912) { src = co2; loc = g - 262144; K = 256; Kpad = 256; }
        else if (g < 325632) { src = dh1; loc = g - 294912; K = 160; Kpad = 192; }
        else if (g < 356352) { src = dh2; loc = g - 325632; K = 160; Kpad = 192; }
        else if (g < 380928) { src = dh3; loc = g - 356352; K = 160; Kpad = 192; }
        else                 { src = sh1; loc = g - 380928; K = 128; Kpad = 128; }
        int r = loc / Kpad, c = loc - r * Kpad;
        float x = (c < K) ? src[r * K + c] : 0.f;
        __half h, l; splitf(x, h, l);
        dhi[g] = h; dlo[g] = l;
    } else {
        __shared__ float tile[32][33];
        int b2 = bid - PREP_BLKS;
        int c0 = (b2 >> 8) * 32;
        int n0 = (b2 & 255) * 32;
        #pragma unroll
        for (int i = 0; i < 32; i += 8)
            tile[threadIdx.y + i][threadIdx.x] = rgbf[(c0 + threadIdx.y + i) * NR + n0 + threadIdx.x];
        __syncthreads();
        #pragma unroll
        for (int i = 0; i < 32; i += 8) {
            float v = tile[threadIdx.x][threadIdx.y + i];
            __half h, l; splitf(v, h, l);
            size_t o = (size_t)(n0 + threadIdx.y + i) * 128 + c0 + threadIdx.x;
            rgbTH[o] = h; rgbTL[o] = l;
        }
    }
}

// ============================ 3-NN: 256 blocks, 4 threads/point ============================
__global__ __launch_bounds__(256) void knn_kernel(const float* __restrict__ pcd,
                                                  const float* __restrict__ rgb,
                                                  int* __restrict__ outIdx)
{
    __shared__ float4 srgb[2048];
    __shared__ float  md[256 * 3];
    __shared__ int    mi[256 * 3];
    int tid = threadIdx.x;
    int pl  = tid & 63;                 // point lane
    int q   = tid >> 6;                 // quadrant 0..3 (indices == q mod 4)
    int p   = blockIdx.x * 64 + pl;
    float px = pcd[p * 3 + 0], py = pcd[p * 3 + 1], pz = pcd[p * 3 + 2];
    float b0 = 1e30f, b1 = 1e30f, b2 = 1e30f;
    int i0 = 0, i1 = 0, i2 = 0;
    for (int t = 0; t < NR; t += 2048) {
        __syncthreads();
        for (int e = tid; e < 2048; e += 256) {
            int j = t + e;
            srgb[e] = make_float4(rgb[j * 3 + 0], rgb[j * 3 + 1], rgb[j * 3 + 2], 0.f);
        }
        __syncthreads();
        #pragma unroll 8
        for (int i = 0; i < 512; i++) {
            int e = (i << 2) | q;
            float4 rr = srgb[e];
            float dx = px - rr.x, dy = py - rr.y, dz = pz - rr.z;
            float d2 = dx * dx; d2 = fmaf(dy, dy, d2); d2 = fmaf(dz, dz, d2);
            if (d2 < b2) {
                int idx = t + e;
                if (d2 < b0)      { b2 = b1; i2 = i1; b1 = b0; i1 = i0; b0 = d2; i0 = idx; }
                else if (d2 < b1) { b2 = b1; i2 = i1; b1 = d2; i1 = idx; }
                else              { b2 = d2; i2 = idx; }
            }
        }
    }
    md[tid * 3 + 0] = b0; md[tid * 3 + 1] = b1; md[tid * 3 + 2] = b2;
    mi[tid * 3 + 0] = i0; mi[tid * 3 + 1] = i1; mi[tid * 3 + 2] = i2;
    __syncthreads();
    if (tid < 64) {
        // 4-way merge over quadrant lists, ordered by (d2, idx) = top_k stable rule.
        int ptr[4] = {0, 0, 0, 0};
        #pragma unroll
        for (int t3 = 0; t3 < 3; t3++) {
            float best = 3.4e38f; int bq = 0, bidx = 0x7fffffff;
            #pragma unroll
            for (int qq = 0; qq < 4; qq++) {
                if (ptr[qq] < 3) {
                    int rr = (qq * 64 + tid) * 3 + ptr[qq];
                    float d = md[rr]; int ix = mi[rr];
                    if (d < best || (d == best && ix < bidx)) { best = d; bq = qq; bidx = ix; }
                }
            }
            ptr[bq]++;
            outIdx[p * 3 + t3] = (sqrtf(best) > 0.075f) ? -1 : bidx;
        }
    }
}

// ============================ staging kernels ============================
__global__ void tpose_pcd(const float* __restrict__ in,
                          __half* __restrict__ outH, __half* __restrict__ outL)
{
    __shared__ float t[32][33];
    int n0 = blockIdx.x * 32;
    int tx = threadIdx.x, ty = threadIdx.y;
    #pragma unroll
    for (int i = 0; i < 32; i += 8) t[ty + i][tx] = in[(ty + i) * NP + n0 + tx];
    __syncthreads();
    #pragma unroll
    for (int i = 0; i < 32; i += 8) {
        float v = t[tx][ty + i];
        __half h, l; splitf(v, h, l);
        size_t o = (size_t)(n0 + ty + i) * 160 + tx;
        outH[o] = h; outL[o] = l;
    }
}

__global__ __launch_bounds__(256) void gather_kernel(
    const __half* __restrict__ rgbTH, const __half* __restrict__ rgbTL,
    const int* __restrict__ idx,
    __half* __restrict__ xcatH, __half* __restrict__ xcatL)
{
    int e = blockIdx.x * 256 + threadIdx.x;
    int c4 = e & 31;
    int t = e >> 5;
    int p = t / 3, j = t - p * 3;
    int row = idx[p * 3 + j];
    uint2 vh = make_uint2(0u, 0u), vl = make_uint2(0u, 0u);
    if (row >= 0) {
        vh = *(const uint2*)(rgbTH + (size_t)row * 128 + c4 * 4);
        vl = *(const uint2*)(rgbTL + (size_t)row * 128 + c4 * 4);
    }
    size_t o = (size_t)p * 384 + j * 128 + c4 * 4;
    *(uint2*)(xcatH + o) = vh;
    *(uint2*)(xcatL + o) = vl;
}

__global__ __launch_bounds__(256) void maxfeat_kernel(
    const __half* __restrict__ rgbTH, const __half* __restrict__ rgbTL,
    const int* __restrict__ idx,
    __half* __restrict__ buf2H, __half* __restrict__ buf2L)
{
    int e = blockIdx.x * 256 + threadIdx.x;
    int c4 = e & 31;
    int p = e >> 5;
    float m[4] = {-1e30f, -1e30f, -1e30f, -1e30f};
    #pragma unroll
    for (int j = 0; j < 3; j++) {
        int row = idx[p * 3 + j];
        float v[4] = {0.f, 0.f, 0.f, 0.f};
        if (row >= 0) {
            const __half* ph = rgbTH + (size_t)row * 128 + c4 * 4;
            const __half* pl = rgbTL + (size_t)row * 128 + c4 * 4;
            #pragma unroll
            for (int q = 0; q < 4; q++)
                v[q] = __half2float(ph[q]) + __half2float(pl[q]);
        }
        #pragma unroll
        for (int q = 0; q < 4; q++) m[q] = fmaxf(m[q], v[q]);
    }
    __half hh[4], ll[4];
    #pragma unroll
    for (int q = 0; q < 4; q++) splitf(m[q], hh[q], ll[q]);
    size_t o = (size_t)p * 256 + 128 + c4 * 4;
    *(__half2*)(buf2H + o)     = __halves2half2(hh[0], hh[1]);
    *(__half2*)(buf2H + o + 2) = __halves2half2(hh[2], hh[3]);
    *(__half2*)(buf2L + o)     = __halves2half2(ll[0], ll[1]);
    *(__half2*)(buf2L + o + 2) = __halves2half2(ll[2], ll[3]);
}

// ============================ HMMA GEMM (128x128, cp.async, ldmatrix, fp32 acc) ============================
// Y[p, m] = sum_k X[p,k] * W[m,k]; X/W fp16 hi/lo planes; acc = XhWh + XlWh + XhWl (fp32).
#define LDW 40
#define PLANE (128 * LDW)
#define STG   (4 * PLANE)
#define AH 0
#define AL PLANE
#define BH (2 * PLANE)
#define BL (3 * PLANE)
__global__ __launch_bounds__(256, 2) void gemm_hmma(
    const __half* __restrict__ Xh, const __half* __restrict__ Xl, int pitchA, int K,
    const __half* __restrict__ Whi, const __half* __restrict__ Wlo, int Wpitch, int Cout,
    __half* __restrict__ Yh, __half* __restrict__ Yl, int pitchY,
    float* __restrict__ Yf, int pitchYf,
    const float* __restrict__ bias, const float* __restrict__ bn, int mode)
{
    extern __shared__ __half sdyn[];
    __shared__ float sSc[128], sSh[128];

    const int tid = threadIdx.x;
    const int lane = tid & 31, wid = tid >> 5;
    const int wm = wid >> 1, wn = wid & 1;
    const int g = lane >> 2, tc = lane & 3;
    const int n0 = blockIdx.x * 128;
    const int nb0 = blockIdx.y * 128;
    const int NT = min(128, Cout - nb0);

    if (tid < 128) {
        float sc = 0.f, sh = 0.f;
        if (tid < NT) {
            int m = nb0 + tid;
            float b = bias[m];
            sc = 1.f; sh = b;
            if (mode) {
                float gg = bn[m], be = bn[Cout + m], mn = bn[2 * Cout + m], v = bn[3 * Cout + m];
                float inv = gg * rsqrtf(v + 1e-5f);
                sc = inv; sh = (b - mn) * inv + be;
            }
        }
        sSc[tid] = sc; sSh[tid] = sh;
    }

    float acc[2][8][4];
    #pragma unroll
    for (int a = 0; a < 2; a++)
        #pragma unroll
        for (int b = 0; b < 8; b++)
            #pragma unroll
            for (int c = 0; c < 4; c++) acc[a][b][c] = 0.f;

    const int r0c = tid >> 2,         o0c = (tid & 3) * 8;
    const int r1c = (tid + 256) >> 2, o1c = ((tid + 256) & 3) * 8;
    const unsigned sbase = (unsigned)__cvta_generic_to_shared(sdyn);

    const int slabs = K >> 5;

    #define LOAD_SLAB(sl) do {                                                      \
        int k0_ = (sl) << 5;                                                        \
        unsigned sb_ = sbase + ((sl) & 1) * (STG * 2);                              \
        cpa16(sb_ + (AH + r0c * LDW + o0c) * 2, Xh + (size_t)(n0 + r0c) * pitchA + k0_ + o0c);  \
        cpa16(sb_ + (AH + r1c * LDW + o1c) * 2, Xh + (size_t)(n0 + r1c) * pitchA + k0_ + o1c);  \
        cpa16(sb_ + (AL + r0c * LDW + o0c) * 2, Xl + (size_t)(n0 + r0c) * pitchA + k0_ + o0c);  \
        cpa16(sb_ + (AL + r1c * LDW + o1c) * 2, Xl + (size_t)(n0 + r1c) * pitchA + k0_ + o1c);  \
        cpa16(sb_ + (BH + r0c * LDW + o0c) * 2, Whi + (size_t)(nb0 + r0c) * Wpitch + k0_ + o0c); \
        cpa16(sb_ + (BH + r1c * LDW + o1c) * 2, Whi + (size_t)(nb0 + r1c) * Wpitch + k0_ + o1c); \
        cpa16(sb_ + (BL + r0c * LDW + o0c) * 2, Wlo + (size_t)(nb0 + r0c) * Wpitch + k0_ + o0c); \
        cpa16(sb_ + (BL + r1c * LDW + o1c) * 2, Wlo + (size_t)(nb0 + r1c) * Wpitch + k0_ + o1c); \
        cpa_commit();                                                               \
    } while (0)

    const int arow = wm * 32 + (lane & 15);
    const int akk0 = (lane >> 4) * 8;
    const int brow = wn * 64 + ((lane >> 4) << 3) + (lane & 7);
    const int bkk0 = ((lane >> 3) & 1) * 8;

    LOAD_SLAB(0);
    for (int sl = 0; sl < slabs; sl++) {
        cpa_wait0();
        __syncthreads();
        if (sl + 1 < slabs) LOAD_SLAB(sl + 1);

        const unsigned stb = sbase + (sl & 1) * (STG * 2);
        #pragma unroll
        for (int s = 0; s < 2; s++) {
            const int akk = s * 16 + akk0;
            const int bkk = s * 16 + bkk0;
            unsigned ah[2][4], al[2][4];
            #pragma unroll
            for (int mt = 0; mt < 2; mt++) {
                unsigned off = ((arow + mt * 16) * LDW + akk) * 2;
                ldm4(ah[mt], stb + (AH * 2) + off);
                ldm4(al[mt], stb + (AL * 2) + off);
            }
            #pragma unroll
            for (int jp = 0; jp < 4; jp++) {
                unsigned boff = ((brow + jp * 16) * LDW + bkk) * 2;
                unsigned bh[4], bl[4];
                ldm4(bh, stb + (BH * 2) + boff);
                ldm4(bl, stb + (BL * 2) + boff);
                #pragma unroll
                for (int h = 0; h < 2; h++) {
                    int nt = jp * 2 + h;
                    #pragma unroll
                    for (int mt = 0; mt < 2; mt++) {
                        mma16816(acc[mt][nt], ah[mt], bh + 2 * h);
                        mma16816(acc[mt][nt], al[mt], bh + 2 * h);
                        mma16816(acc[mt][nt], ah[mt], bl + 2 * h);
                    }
                }
            }
        }
        __syncthreads();
    }

    // --- epilogue ---
    #pragma unroll
    for (int mt = 0; mt < 2; mt++) {
        int r0 = n0 + wm * 32 + mt * 16 + g;
        #pragma unroll
        for (int nt = 0; nt < 8; nt++) {
            int col = wn * 64 + nt * 8 + tc * 2;
            if (col < NT) {
                float sc0 = sSc[col], sh0 = sSh[col];
                float sc1 = sSc[col + 1], sh1 = sSh[col + 1];
                float* a = acc[mt][nt];
                float y0 = a[0] * sc0 + sh0;
                float y1 = a[1] * sc1 + sh1;
                float y2 = a[2] * sc0 + sh0;
                float y3 = a[3] * sc1 + sh1;
                if (mode) {
                    y0 = fmaxf(y0, 0.f); y1 = fmaxf(y1, 0.f);
                    y2 = fmaxf(y2, 0.f); y3 = fmaxf(y3, 0.f);
                }
                if (Yf) {
                    *(float2*)(Yf + (size_t)r0 * pitchYf + nb0 + col)       = make_float2(y0, y1);
                    *(float2*)(Yf + (size_t)(r0 + 8) * pitchYf + nb0 + col) = make_float2(y2, y3);
                }
                if (Yh) {
                    __half h0, l0, h1, l1, h2, l2, h3, l3;
                    splitf(y0, h0, l0); splitf(y1, h1, l1);
                    splitf(y2, h2, l2); splitf(y3, h3, l3);
                    *(__half2*)(Yh + (size_t)r0 * pitchY + nb0 + col)       = __halves2half2(h0, h1);
                    *(__half2*)(Yh + (size_t)(r0 + 8) * pitchY + nb0 + col) = __halves2half2(h2, h3);
                    *(__half2*)(Yl + (size_t)r0 * pitchY + nb0 + col)       = __halves2half2(l0, l1);
                    *(__half2*)(Yl + (size_t)(r0 + 8) * pitchY + nb0 + col) = __halves2half2(l2, l3);
                }
            }
        }
    }
}

// ============================ heads ============================
__global__ __launch_bounds__(256) void score_kernel(const float* __restrict__ s,
                                                    const float* __restrict__ w,
                                                    const float* __restrict__ b,
                                                    float* __restrict__ out)
{
    int wid = threadIdx.x >> 5, lid = threadIdx.x & 31;
    int p = blockIdx.x * 8 + wid;
    float4 v = *(const float4*)(s + (size_t)p * 128 + lid * 4);
    float4 ww = *(const float4*)(w + lid * 4);
    float sum = v.x * ww.x + v.y * ww.y + v.z * ww.z + v.w * ww.w;
    #pragma unroll
    for (int o = 16; o > 0; o >>= 1) sum += __shfl_xor_sync(0xffffffff, sum, o);
    if (lid == 0) out[p] = 1.f / (1.f + expf(-(sum + b[0])));
}

__global__ __launch_bounds__(256) void normalize_kernel(const float* __restrict__ fp,
                                                        float* __restrict__ out)
{
    int wid = threadIdx.x >> 5, lid = threadIdx.x & 31;
    int p = blockIdx.x * 8 + wid;
    float4 v = *(const float4*)(fp + (size_t)p * 128 + lid * 4);
    float ss = v.x * v.x + v.y * v.y + v.z * v.z + v.w * v.w;
    #pragma unroll
    for (int o = 16; o > 0; o >>= 1) ss += __shfl_xor_sync(0xffffffff, ss, o);
    float inv = 1.f / fmaxf(sqrtf(ss), 1e-12f);
    float4 r = make_float4(v.x * inv, v.y * inv, v.z * inv, v.w * inv);
    *(float4*)(out + (size_t)p * 128 + lid * 4) = r;
}

// ============================ launch ============================
extern "C" void kernel_launch(void* const* d_in, const int* in_sizes, int n_in,
                              void* d_out, int out_size)
{
    const float* pcd_xyz  = (const float*)d_in[0];
    const float* rgb_xyz  = (const float*)d_in[1];
    const float* pcd_feat = (const float*)d_in[2];
    const float* rgb_feat = (const float*)d_in[3];
    const float* cc1_w = (const float*)d_in[4];
    const float* cc1_b = (const float*)d_in[5];
    const float* cc_bn = (const float*)d_in[6];
    const float* cc2_w = (const float*)d_in[7];
    const float* cc2_b = (const float*)d_in[8];
    const float* co1_w = (const float*)d_in[9];
    const float* co1_b = (const float*)d_in[10];
    const float* co_bn = (const float*)d_in[11];
    const float* co2_w = (const float*)d_in[12];
    const float* co2_b = (const float*)d_in[13];
    const float* dh1_w = (const float*)d_in[14];
    const float* dh1_b = (const float*)d_in[15];
    const float* dh1_bn = (const float*)d_in[16];
    const float* dh2_w = (const float*)d_in[17];
    const float* dh2_b = (const float*)d_in[18];
    const float* dh2_bn = (const float*)d_in[19];
    const float* dh3_w = (const float*)d_in[20];
    const float* dh3_b = (const float*)d_in[21];
    const float* sh1_w = (const float*)d_in[22];
    const float* sh1_b = (const float*)d_in[23];
    const float* sh_bn = (const float*)d_in[24];
    const float* sh2_w = (const float*)d_in[25];
    const float* sh2_b = (const float*)d_in[26];

    __half *xcH, *xcL, *h1H, *h1L, *b2H, *b2L, *coH, *coL, *fuH, *fuL;
    __half *d1H, *d1L, *d2H, *d2L, *fpH, *fpL, *rgH, *rgL, *whi, *wlo;
    float *fpF, *s1F;
    int* idx;
    cudaGetSymbolAddress((void**)&xcH, g_xcatH); cudaGetSymbolAddress((void**)&xcL, g_xcatL);
    cudaGetSymbolAddress((void**)&h1H, g_h1H);   cudaGetSymbolAddress((void**)&h1L, g_h1L);
    cudaGetSymbolAddress((void**)&b2H, g_buf2H); cudaGetSymbolAddress((void**)&b2L, g_buf2L);
    cudaGetSymbolAddress((void**)&coH, g_co1H);  cudaGetSymbolAddress((void**)&coL, g_co1L);
    cudaGetSymbolAddress((void**)&fuH, g_fullH); cudaGetSymbolAddress((void**)&fuL, g_fullL);
    cudaGetSymbolAddress((void**)&d1H, g_d1H);   cudaGetSymbolAddress((void**)&d1L, g_d1L);
    cudaGetSymbolAddress((void**)&d2H, g_d2H);   cudaGetSymbolAddress((void**)&d2L, g_d2L);
    cudaGetSymbolAddress((void**)&fpH, g_fpH);   cudaGetSymbolAddress((void**)&fpL, g_fpL);
    cudaGetSymbolAddress((void**)&rgH, g_rgbTH); cudaGetSymbolAddress((void**)&rgL, g_rgbTL);
    cudaGetSymbolAddress((void**)&fpF, g_fpF);   cudaGetSymbolAddress((void**)&s1F, g_s1F);
    cudaGetSymbolAddress((void**)&whi, g_whi);   cudaGetSymbolAddress((void**)&wlo, g_wlo);
    cudaGetSymbolAddress((void**)&idx, g_idx);

    float* out = (float*)d_out;

    const int SMEM = 2 * STG * 2;   // 81920 bytes
    cudaFuncSetAttribute(gemm_hmma, cudaFuncAttributeMaxDynamicSharedMemorySize, SMEM);

    const int O_CC1 = 0,      O_CC2 = 147456, O_CO1 = 196608, O_CO2 = 262144;
    const int O_DH1 = 294912, O_DH2 = 325632, O_DH3 = 356352, O_SH1 = 380928;

    // order chosen so cc1 is the 4th launch (ncu -s 5 -c 1 captures it)
    prep_misc<<<PREP_BLKS + 1024, dim3(32, 8)>>>(cc1_w, cc2_w, co1_w, co2_w,
                                                 dh1_w, dh2_w, dh3_w, sh1_w, whi, wlo,
                                                 rgb_feat, rgH, rgL);
    knn_kernel<<<NP / 64, 256>>>(pcd_xyz, rgb_xyz, idx);
    gather_kernel<<<NP * 3 * 32 / 256, 256>>>(rgH, rgL, idx, xcH, xcL);

    gemm_hmma<<<dim3(128, 3), 256, SMEM>>>(xcH, xcL, 384, 384, whi + O_CC1, wlo + O_CC1, 384, 384,
                                           h1H, h1L, 384, nullptr, 0, cc1_b, cc_bn, 1);

    maxfeat_kernel<<<NP * 32 / 256, 256>>>(rgH, rgL, idx, b2H, b2L);
    tpose_pcd<<<NP / 32, dim3(32, 8)>>>(pcd_feat, fuH, fuL);

    gemm_hmma<<<dim3(128, 1), 256, SMEM>>>(h1H, h1L, 384, 384, whi + O_CC2, wlo + O_CC2, 384, 128,
                                           b2H, b2L, 256, nullptr, 0, cc2_b, nullptr, 0);
    gemm_hmma<<<dim3(128, 2), 256, SMEM>>>(b2H, b2L, 256, 256, whi + O_CO1, wlo + O_CO1, 256, 256,
                                           coH, coL, 256, nullptr, 0, co1_b, co_bn, 1);
    gemm_hmma<<<dim3(128, 1), 256, SMEM>>>(coH, coL, 256, 256, whi + O_CO2, wlo + O_CO2, 256, 128,
                                           fuH + 32, fuL + 32, 160, nullptr, 0, co2_b, nullptr, 0);
    gemm_hmma<<<dim3(128, 2), 256, SMEM>>>(fuH, fuL, 160, 160, whi + O_DH1, wlo + O_DH1, 192, 160,
                                           d1H, d1L, 160, nullptr, 0, dh1_b, dh1_bn, 1);
    gemm_hmma<<<dim3(128, 2), 256, SMEM>>>(d1H, d1L, 160, 160, whi + O_DH2, wlo + O_DH2, 192, 160,
                                           d2H, d2L, 160, nullptr, 0, dh2_b, dh2_bn, 1);
    gemm_hmma<<<dim3(128, 1), 256, SMEM>>>(d2H, d2L, 160, 160, whi + O_DH3, wlo + O_DH3, 192, 128,
                                           fpH, fpL, 128, fpF, 128, dh3_b, nullptr, 0);
    gemm_hmma<<<dim3(128, 1), 256, SMEM>>>(fpH, fpL, 128, 128, whi + O_SH1, wlo + O_SH1, 128, 128,
                                           nullptr, nullptr, 0, s1F, 128, sh1_b, sh_bn, 1);

    // outputs: [pcd_xyz (NP*3)] [vote_scores (NP)] [vf (NP,128)]
    score_kernel<<<NP / 8, 256>>>(s1F, sh2_w, sh2_b, out + NP * 3);
    normalize_kernel<<<NP / 8, 256>>>(fpF, out + NP * 3 + NP);
    cudaMemcpyAsync(out, pcd_xyz, NP * 3 * sizeof(float), cudaMemcpyDeviceToDevice, 0);
}

// round 16
// speedup vs baseline: 1.1484x; 1.0304x over previous
#include <cuda_runtime.h>
#include <cuda_fp16.h>
#include <math.h>

#define NP 16384
#define NR 8192

typedef unsigned long long ull;

// ============================ scratch buffers ============================
__device__ __align__(16) __half g_xcatH[(size_t)NP * 384];
__device__ __align__(16) __half g_xcatL[(size_t)NP * 384];
__device__ __align__(16) __half g_h1H  [(size_t)NP * 384];
__device__ __align__(16) __half g_h1L  [(size_t)NP * 384];
__device__ __align__(16) __half g_buf2H[(size_t)NP * 256];   // cols 0-127 cc2, 128-255 maxfeat
__device__ __align__(16) __half g_buf2L[(size_t)NP * 256];
__device__ __align__(16) __half g_co1H [(size_t)NP * 256];
__device__ __align__(16) __half g_co1L [(size_t)NP * 256];
__device__ __align__(16) __half g_fullH[(size_t)NP * 160];   // cols 0-31 pcd, 32-159 attach
__device__ __align__(16) __half g_fullL[(size_t)NP * 160];
__device__ __align__(16) __half g_d1H  [(size_t)NP * 160];
__device__ __align__(16) __half g_d1L  [(size_t)NP * 160];
__device__ __align__(16) __half g_d2H  [(size_t)NP * 160];
__device__ __align__(16) __half g_d2L  [(size_t)NP * 160];
__device__ __align__(16) __half g_fpH  [(size_t)NP * 128];
__device__ __align__(16) __half g_fpL  [(size_t)NP * 128];
__device__ __align__(16) float  g_fpF  [(size_t)NP * 128];
__device__ __align__(16) float  g_s1F  [(size_t)NP * 128];
__device__ __align__(16) __half g_rgbTH[(size_t)NR * 128];
__device__ __align__(16) __half g_rgbTL[(size_t)NR * 128];
__device__ int g_idx[NP * 3];
#define WTOT 397312
__device__ __align__(16) __half g_whi[WTOT];
__device__ __align__(16) __half g_wlo[WTOT];

// ============================ helpers ============================
__device__ __forceinline__ void splitf(float x, __half& h, __half& l) {
    h = __float2half(x);
    l = __float2half(x - __half2float(h));
}
__device__ __forceinline__ void mma16816(float* d, const unsigned* a, const unsigned* b) {
    asm volatile("mma.sync.aligned.m16n8k16.row.col.f32.f16.f16.f32 "
        "{%0,%1,%2,%3}, {%4,%5,%6,%7}, {%8,%9}, {%0,%1,%2,%3};"
        : "+f"(d[0]), "+f"(d[1]), "+f"(d[2]), "+f"(d[3])
        : "r"(a[0]), "r"(a[1]), "r"(a[2]), "r"(a[3]), "r"(b[0]), "r"(b[1]));
}
__device__ __forceinline__ void ldm4(unsigned* r, unsigned addr) {
    asm volatile("ldmatrix.sync.aligned.m8n8.x4.shared.b16 {%0,%1,%2,%3}, [%4];"
        : "=r"(r[0]), "=r"(r[1]), "=r"(r[2]), "=r"(r[3]) : "r"(addr));
}
__device__ __forceinline__ void cpa16(unsigned dst, const void* src) {
    asm volatile("cp.async.cg.shared.global [%0], [%1], 16;" :: "r"(dst), "l"(src));
}
__device__ __forceinline__ void cpa_commit() {
    asm volatile("cp.async.commit_group;" ::: "memory");
}
__device__ __forceinline__ void cpa_wait0() {
    asm volatile("cp.async.wait_group 0;" ::: "memory");
}

// ============================ fused prep: weight split + rgb transpose + pcd transpose ============================
#define PREP_BLKS ((WTOT + 255) / 256)
__global__ void prep_misc(
    const float* __restrict__ cc1, const float* __restrict__ cc2,
    const float* __restrict__ co1, const float* __restrict__ co2,
    const float* __restrict__ dh1, const float* __restrict__ dh2,
    const float* __restrict__ dh3, const float* __restrict__ sh1,
    __half* __restrict__ dhi, __half* __restrict__ dlo,
    const float* __restrict__ rgbf,
    __half* __restrict__ rgbTH, __half* __restrict__ rgbTL,
    const float* __restrict__ pcdf,
    __half* __restrict__ fullH, __half* __restrict__ fullL)
{
    int bid = blockIdx.x;
    if (bid < PREP_BLKS) {
        int g = bid * 256 + threadIdx.y * 32 + threadIdx.x;
        if (g >= WTOT) return;
        const float* src; int loc, K, Kpad;
        if      (g < 147456) { src = cc1; loc = g;          K = 384; Kpad = 384; }
        else if (g < 196608) { src = cc2; loc = g - 147456; K = 384; Kpad = 384; }
        else if (g < 262144) { src = co1; loc = g - 196608; K = 256; Kpad = 256; }
        else if (g < 294912) { src = co2; loc = g - 262144; K = 256; Kpad = 256; }
        else if (g < 325632) { src = dh1; loc = g - 294912; K = 160; Kpad = 192; }
        else if (g < 356352) { src = dh2; loc = g - 325632; K = 160; Kpad = 192; }
        else if (g < 380928) { src = dh3; loc = g - 356352; K = 160; Kpad = 192; }
        else                 { src = sh1; loc = g - 380928; K = 128; Kpad = 128; }
        int r = loc / Kpad, c = loc - r * Kpad;
        float x = (c < K) ? src[r * K + c] : 0.f;
        __half h, l; splitf(x, h, l);
        dhi[g] = h; dlo[g] = l;
    } else if (bid < PREP_BLKS + 1024) {
        __shared__ float tile[32][33];
        int b2 = bid - PREP_BLKS;
        int c0 = (b2 >> 8) * 32;
        int n0 = (b2 & 255) * 32;
        #pragma unroll
        for (int i = 0; i < 32; i += 8)
            tile[threadIdx.y + i][threadIdx.x] = rgbf[(c0 + threadIdx.y + i) * NR + n0 + threadIdx.x];
        __syncthreads();
        #pragma unroll
        for (int i = 0; i < 32; i += 8) {
            float v = tile[threadIdx.x][threadIdx.y + i];
            __half h, l; splitf(v, h, l);
            size_t o = (size_t)(n0 + threadIdx.y + i) * 128 + c0 + threadIdx.x;
            rgbTH[o] = h; rgbTL[o] = l;
        }
    } else {
        __shared__ float t[32][33];
        int b3 = bid - PREP_BLKS - 1024;    // 0..511
        int n0 = b3 * 32;
        int tx = threadIdx.x, ty = threadIdx.y;
        #pragma unroll
        for (int i = 0; i < 32; i += 8) t[ty + i][tx] = pcdf[(ty + i) * NP + n0 + tx];
        __syncthreads();
        #pragma unroll
        for (int i = 0; i < 32; i += 8) {
            float v = t[tx][ty + i];
            __half h, l; splitf(v, h, l);
            size_t o = (size_t)(n0 + ty + i) * 160 + tx;
            fullH[o] = h; fullL[o] = l;
        }
    }
}

// ============================ 3-NN: 256 blocks, 4 threads/point ============================
__global__ __launch_bounds__(256) void knn_kernel(const float* __restrict__ pcd,
                                                  const float* __restrict__ rgb,
                                                  int* __restrict__ outIdx)
{
    __shared__ float4 srgb[2048];
    __shared__ float  md[256 * 3];
    __shared__ int    mi[256 * 3];
    int tid = threadIdx.x;
    int pl  = tid & 63;
    int q   = tid >> 6;
    int p   = blockIdx.x * 64 + pl;
    float px = pcd[p * 3 + 0], py = pcd[p * 3 + 1], pz = pcd[p * 3 + 2];
    float b0 = 1e30f, b1 = 1e30f, b2 = 1e30f;
    int i0 = 0, i1 = 0, i2 = 0;
    for (int t = 0; t < NR; t += 2048) {
        __syncthreads();
        for (int e = tid; e < 2048; e += 256) {
            int j = t + e;
            srgb[e] = make_float4(rgb[j * 3 + 0], rgb[j * 3 + 1], rgb[j * 3 + 2], 0.f);
        }
        __syncthreads();
        #pragma unroll 8
        for (int i = 0; i < 512; i++) {
            int e = (i << 2) | q;
            float4 rr = srgb[e];
            float dx = px - rr.x, dy = py - rr.y, dz = pz - rr.z;
            float d2 = dx * dx; d2 = fmaf(dy, dy, d2); d2 = fmaf(dz, dz, d2);
            if (d2 < b2) {
                int idx = t + e;
                if (d2 < b0)      { b2 = b1; i2 = i1; b1 = b0; i1 = i0; b0 = d2; i0 = idx; }
                else if (d2 < b1) { b2 = b1; i2 = i1; b1 = d2; i1 = idx; }
                else              { b2 = d2; i2 = idx; }
            }
        }
    }
    md[tid * 3 + 0] = b0; md[tid * 3 + 1] = b1; md[tid * 3 + 2] = b2;
    mi[tid * 3 + 0] = i0; mi[tid * 3 + 1] = i1; mi[tid * 3 + 2] = i2;
    __syncthreads();
    if (tid < 64) {
        int ptr[4] = {0, 0, 0, 0};
        #pragma unroll
        for (int t3 = 0; t3 < 3; t3++) {
            float best = 3.4e38f; int bq = 0, bidx = 0x7fffffff;
            #pragma unroll
            for (int qq = 0; qq < 4; qq++) {
                if (ptr[qq] < 3) {
                    int rr = (qq * 64 + tid) * 3 + ptr[qq];
                    float d = md[rr]; int ix = mi[rr];
                    if (d < best || (d == best && ix < bidx)) { best = d; bq = qq; bidx = ix; }
                }
            }
            ptr[bq]++;
            outIdx[p * 3 + t3] = (sqrtf(best) > 0.075f) ? -1 : bidx;
        }
    }
}

// ============================ fused gather + maxfeat ============================
// NP*32 threads: thread (p, c4) loads 3 neighbor rows once, writes xcat rows + max.
__global__ __launch_bounds__(256) void gather_max(
    const __half* __restrict__ rgbTH, const __half* __restrict__ rgbTL,
    const int* __restrict__ idx,
    __half* __restrict__ xcatH, __half* __restrict__ xcatL,
    __half* __restrict__ buf2H, __half* __restrict__ buf2L)
{
    int e = blockIdx.x * 256 + threadIdx.x;
    int c4 = e & 31;
    int p = e >> 5;
    float m[4] = {-1e30f, -1e30f, -1e30f, -1e30f};
    #pragma unroll
    for (int j = 0; j < 3; j++) {
        int row = idx[p * 3 + j];
        uint2 vh = make_uint2(0u, 0u), vl = make_uint2(0u, 0u);
        if (row >= 0) {
            vh = *(const uint2*)(rgbTH + (size_t)row * 128 + c4 * 4);
            vl = *(const uint2*)(rgbTL + (size_t)row * 128 + c4 * 4);
        }
        size_t o = (size_t)p * 384 + j * 128 + c4 * 4;
        *(uint2*)(xcatH + o) = vh;
        *(uint2*)(xcatL + o) = vl;
        // reconstruct for max
        __half2 h01 = *(__half2*)&vh.x, h23 = *(__half2*)&vh.y;
        __half2 l01 = *(__half2*)&vl.x, l23 = *(__half2*)&vl.y;
        float v0 = __low2float(h01) + __low2float(l01);
        float v1 = __high2float(h01) + __high2float(l01);
        float v2 = __low2float(h23) + __low2float(l23);
        float v3 = __high2float(h23) + __high2float(l23);
        m[0] = fmaxf(m[0], v0); m[1] = fmaxf(m[1], v1);
        m[2] = fmaxf(m[2], v2); m[3] = fmaxf(m[3], v3);
    }
    __half hh[4], ll[4];
    #pragma unroll
    for (int q = 0; q < 4; q++) splitf(m[q], hh[q], ll[q]);
    size_t o = (size_t)p * 256 + 128 + c4 * 4;
    *(__half2*)(buf2H + o)     = __halves2half2(hh[0], hh[1]);
    *(__half2*)(buf2H + o + 2) = __halves2half2(hh[2], hh[3]);
    *(__half2*)(buf2L + o)     = __halves2half2(ll[0], ll[1]);
    *(__half2*)(buf2L + o + 2) = __halves2half2(ll[2], ll[3]);
}

// ============================ HMMA GEMM (128x128, cp.async, ldmatrix, fp32 acc) ============================
#define LDW 40
#define PLANE (128 * LDW)
#define STG   (4 * PLANE)
#define AH 0
#define AL PLANE
#define BH (2 * PLANE)
#define BL (3 * PLANE)
__global__ __launch_bounds__(256, 2) void gemm_hmma(
    const __half* __restrict__ Xh, const __half* __restrict__ Xl, int pitchA, int K,
    const __half* __restrict__ Whi, const __half* __restrict__ Wlo, int Wpitch, int Cout,
    __half* __restrict__ Yh, __half* __restrict__ Yl, int pitchY,
    float* __restrict__ Yf, int pitchYf,
    const float* __restrict__ bias, const float* __restrict__ bn, int mode)
{
    extern __shared__ __half sdyn[];
    __shared__ float sSc[128], sSh[128];

    const int tid = threadIdx.x;
    const int lane = tid & 31, wid = tid >> 5;
    const int wm = wid >> 1, wn = wid & 1;
    const int g = lane >> 2, tc = lane & 3;
    const int n0 = blockIdx.x * 128;
    const int nb0 = blockIdx.y * 128;
    const int NT = min(128, Cout - nb0);

    if (tid < 128) {
        float sc = 0.f, sh = 0.f;
        if (tid < NT) {
            int m = nb0 + tid;
            float b = bias[m];
            sc = 1.f; sh = b;
            if (mode) {
                float gg = bn[m], be = bn[Cout + m], mn = bn[2 * Cout + m], v = bn[3 * Cout + m];
                float inv = gg * rsqrtf(v + 1e-5f);
                sc = inv; sh = (b - mn) * inv + be;
            }
        }
        sSc[tid] = sc; sSh[tid] = sh;
    }

    float acc[2][8][4];
    #pragma unroll
    for (int a = 0; a < 2; a++)
        #pragma unroll
        for (int b = 0; b < 8; b++)
            #pragma unroll
            for (int c = 0; c < 4; c++) acc[a][b][c] = 0.f;

    const int r0c = tid >> 2,         o0c = (tid & 3) * 8;
    const int r1c = (tid + 256) >> 2, o1c = ((tid + 256) & 3) * 8;
    const unsigned sbase = (unsigned)__cvta_generic_to_shared(sdyn);

    const int slabs = K >> 5;

    #define LOAD_SLAB(sl) do {                                                      \
        int k0_ = (sl) << 5;                                                        \
        unsigned sb_ = sbase + ((sl) & 1) * (STG * 2);                              \
        cpa16(sb_ + (AH + r0c * LDW + o0c) * 2, Xh + (size_t)(n0 + r0c) * pitchA + k0_ + o0c);  \
        cpa16(sb_ + (AH + r1c * LDW + o1c) * 2, Xh + (size_t)(n0 + r1c) * pitchA + k0_ + o1c);  \
        cpa16(sb_ + (AL + r0c * LDW + o0c) * 2, Xl + (size_t)(n0 + r0c) * pitchA + k0_ + o0c);  \
        cpa16(sb_ + (AL + r1c * LDW + o1c) * 2, Xl + (size_t)(n0 + r1c) * pitchA + k0_ + o1c);  \
        cpa16(sb_ + (BH + r0c * LDW + o0c) * 2, Whi + (size_t)(nb0 + r0c) * Wpitch + k0_ + o0c); \
        cpa16(sb_ + (BH + r1c * LDW + o1c) * 2, Whi + (size_t)(nb0 + r1c) * Wpitch + k0_ + o1c); \
        cpa16(sb_ + (BL + r0c * LDW + o0c) * 2, Wlo + (size_t)(nb0 + r0c) * Wpitch + k0_ + o0c); \
        cpa16(sb_ + (BL + r1c * LDW + o1c) * 2, Wlo + (size_t)(nb0 + r1c) * Wpitch + k0_ + o1c); \
        cpa_commit();                                                               \
    } while (0)

    const int arow = wm * 32 + (lane & 15);
    const int akk0 = (lane >> 4) * 8;
    const int brow = wn * 64 + ((lane >> 4) << 3) + (lane & 7);
    const int bkk0 = ((lane >> 3) & 1) * 8;

    LOAD_SLAB(0);
    for (int sl = 0; sl < slabs; sl++) {
        cpa_wait0();
        __syncthreads();
        if (sl + 1 < slabs) LOAD_SLAB(sl + 1);

        const unsigned stb = sbase + (sl & 1) * (STG * 2);
        #pragma unroll
        for (int s = 0; s < 2; s++) {
            const int akk = s * 16 + akk0;
            const int bkk = s * 16 + bkk0;
            unsigned ah[2][4], al[2][4];
            #pragma unroll
            for (int mt = 0; mt < 2; mt++) {
                unsigned off = ((arow + mt * 16) * LDW + akk) * 2;
                ldm4(ah[mt], stb + (AH * 2) + off);
                ldm4(al[mt], stb + (AL * 2) + off);
            }
            #pragma unroll
            for (int jp = 0; jp < 4; jp++) {
                unsigned boff = ((brow + jp * 16) * LDW + bkk) * 2;
                unsigned bh[4], bl[4];
                ldm4(bh, stb + (BH * 2) + boff);
                ldm4(bl, stb + (BL * 2) + boff);
                #pragma unroll
                for (int h = 0; h < 2; h++) {
                    int nt = jp * 2 + h;
                    #pragma unroll
                    for (int mt = 0; mt < 2; mt++) {
                        mma16816(acc[mt][nt], ah[mt], bh + 2 * h);
                        mma16816(acc[mt][nt], al[mt], bh + 2 * h);
                        mma16816(acc[mt][nt], ah[mt], bl + 2 * h);
                    }
                }
            }
        }
        __syncthreads();
    }

    // --- epilogue ---
    #pragma unroll
    for (int mt = 0; mt < 2; mt++) {
        int r0 = n0 + wm * 32 + mt * 16 + g;
        #pragma unroll
        for (int nt = 0; nt < 8; nt++) {
            int col = wn * 64 + nt * 8 + tc * 2;
            if (col < NT) {
                float sc0 = sSc[col], sh0 = sSh[col];
                float sc1 = sSc[col + 1], sh1 = sSh[col + 1];
                float* a = acc[mt][nt];
                float y0 = a[0] * sc0 + sh0;
                float y1 = a[1] * sc1 + sh1;
                float y2 = a[2] * sc0 + sh0;
                float y3 = a[3] * sc1 + sh1;
                if (mode) {
                    y0 = fmaxf(y0, 0.f); y1 = fmaxf(y1, 0.f);
                    y2 = fmaxf(y2, 0.f); y3 = fmaxf(y3, 0.f);
                }
                if (Yf) {
                    *(float2*)(Yf + (size_t)r0 * pitchYf + nb0 + col)       = make_float2(y0, y1);
                    *(float2*)(Yf + (size_t)(r0 + 8) * pitchYf + nb0 + col) = make_float2(y2, y3);
                }
                if (Yh) {
                    __half h0, l0, h1, l1, h2, l2, h3, l3;
                    splitf(y0, h0, l0); splitf(y1, h1, l1);
                    splitf(y2, h2, l2); splitf(y3, h3, l3);
                    *(__half2*)(Yh + (size_t)r0 * pitchY + nb0 + col)       = __halves2half2(h0, h1);
                    *(__half2*)(Yh + (size_t)(r0 + 8) * pitchY + nb0 + col) = __halves2half2(h2, h3);
                    *(__half2*)(Yl + (size_t)r0 * pitchY + nb0 + col)       = __halves2half2(l0, l1);
                    *(__half2*)(Yl + (size_t)(r0 + 8) * pitchY + nb0 + col) = __halves2half2(l2, l3);
                }
            }
        }
    }
}

// ============================ fused score + normalize ============================
__global__ __launch_bounds__(256) void score_norm(
    const float* __restrict__ s1, const float* __restrict__ fp,
    const float* __restrict__ w, const float* __restrict__ b,
    float* __restrict__ outScore, float* __restrict__ outVf)
{
    int wid = threadIdx.x >> 5, lid = threadIdx.x & 31;
    int p = blockIdx.x * 8 + wid;
    // normalize fp row
    float4 v = *(const float4*)(fp + (size_t)p * 128 + lid * 4);
    float ss = v.x * v.x + v.y * v.y + v.z * v.z + v.w * v.w;
    // score dot
    float4 sv = *(const float4*)(s1 + (size_t)p * 128 + lid * 4);
    float4 ww = *(const float4*)(w + lid * 4);
    float dt = sv.x * ww.x + sv.y * ww.y + sv.z * ww.z + sv.w * ww.w;
    #pragma unroll
    for (int o = 16; o > 0; o >>= 1) {
        ss += __shfl_xor_sync(0xffffffff, ss, o);
        dt += __shfl_xor_sync(0xffffffff, dt, o);
    }
    float inv = 1.f / fmaxf(sqrtf(ss), 1e-12f);
    *(float4*)(outVf + (size_t)p * 128 + lid * 4) =
        make_float4(v.x * inv, v.y * inv, v.z * inv, v.w * inv);
    if (lid == 0) outScore[p] = 1.f / (1.f + expf(-(dt + b[0])));
}

// ============================ launch ============================
extern "C" void kernel_launch(void* const* d_in, const int* in_sizes, int n_in,
                              void* d_out, int out_size)
{
    const float* pcd_xyz  = (const float*)d_in[0];
    const float* rgb_xyz  = (const float*)d_in[1];
    const float* pcd_feat = (const float*)d_in[2];
    const float* rgb_feat = (const float*)d_in[3];
    const float* cc1_w = (const float*)d_in[4];
    const float* cc1_b = (const float*)d_in[5];
    const float* cc_bn = (const float*)d_in[6];
    const float* cc2_w = (const float*)d_in[7];
    const float* cc2_b = (const float*)d_in[8];
    const float* co1_w = (const float*)d_in[9];
    const float* co1_b = (const float*)d_in[10];
    const float* co_bn = (const float*)d_in[11];
    const float* co2_w = (const float*)d_in[12];
    const float* co2_b = (const float*)d_in[13];
    const float* dh1_w = (const float*)d_in[14];
    const float* dh1_b = (const float*)d_in[15];
    const float* dh1_bn = (const float*)d_in[16];
    const float* dh2_w = (const float*)d_in[17];
    const float* dh2_b = (const float*)d_in[18];
    const float* dh2_bn = (const float*)d_in[19];
    const float* dh3_w = (const float*)d_in[20];
    const float* dh3_b = (const float*)d_in[21];
    const float* sh1_w = (const float*)d_in[22];
    const float* sh1_b = (const float*)d_in[23];
    const float* sh_bn = (const float*)d_in[24];
    const float* sh2_w = (const float*)d_in[25];
    const float* sh2_b = (const float*)d_in[26];

    __half *xcH, *xcL, *h1H, *h1L, *b2H, *b2L, *coH, *coL, *fuH, *fuL;
    __half *d1H, *d1L, *d2H, *d2L, *fpH, *fpL, *rgH, *rgL, *whi, *wlo;
    float *fpF, *s1F;
    int* idx;
    cudaGetSymbolAddress((void**)&xcH, g_xcatH); cudaGetSymbolAddress((void**)&xcL, g_xcatL);
    cudaGetSymbolAddress((void**)&h1H, g_h1H);   cudaGetSymbolAddress((void**)&h1L, g_h1L);
    cudaGetSymbolAddress((void**)&b2H, g_buf2H); cudaGetSymbolAddress((void**)&b2L, g_buf2L);
    cudaGetSymbolAddress((void**)&coH, g_co1H);  cudaGetSymbolAddress((void**)&coL, g_co1L);
    cudaGetSymbolAddress((void**)&fuH, g_fullH); cudaGetSymbolAddress((void**)&fuL, g_fullL);
    cudaGetSymbolAddress((void**)&d1H, g_d1H);   cudaGetSymbolAddress((void**)&d1L, g_d1L);
    cudaGetSymbolAddress((void**)&d2H, g_d2H);   cudaGetSymbolAddress((void**)&d2L, g_d2L);
    cudaGetSymbolAddress((void**)&fpH, g_fpH);   cudaGetSymbolAddress((void**)&fpL, g_fpL);
    cudaGetSymbolAddress((void**)&rgH, g_rgbTH); cudaGetSymbolAddress((void**)&rgL, g_rgbTL);
    cudaGetSymbolAddress((void**)&fpF, g_fpF);   cudaGetSymbolAddress((void**)&s1F, g_s1F);
    cudaGetSymbolAddress((void**)&whi, g_whi);   cudaGetSymbolAddress((void**)&wlo, g_wlo);
    cudaGetSymbolAddress((void**)&idx, g_idx);

    float* out = (float*)d_out;

    const int SMEM = 2 * STG * 2;   // 81920 bytes
    cudaFuncSetAttribute(gemm_hmma, cudaFuncAttributeMaxDynamicSharedMemorySize, SMEM);

    const int O_CC1 = 0,      O_CC2 = 147456, O_CO1 = 196608, O_CO2 = 262144;
    const int O_DH1 = 294912, O_DH2 = 325632, O_DH3 = 356352, O_SH1 = 380928;

    // order chosen so cc1 is the 4th launch (ncu -s 5 -c 1 captures it)
    prep_misc<<<PREP_BLKS + 1024 + 512, dim3(32, 8)>>>(cc1_w, cc2_w, co1_w, co2_w,
                                                       dh1_w, dh2_w, dh3_w, sh1_w, whi, wlo,
                                                       rgb_feat, rgH, rgL,
                                                       pcd_feat, fuH, fuL);
    knn_kernel<<<NP / 64, 256>>>(pcd_xyz, rgb_xyz, idx);
    gather_max<<<NP * 32 / 256, 256>>>(rgH, rgL, idx, xcH, xcL, b2H, b2L);

    gemm_hmma<<<dim3(128, 3), 256, SMEM>>>(xcH, xcL, 384, 384, whi + O_CC1, wlo + O_CC1, 384, 384,
                                           h1H, h1L, 384, nullptr, 0, cc1_b, cc_bn, 1);
    gemm_hmma<<<dim3(128, 1), 256, SMEM>>>(h1H, h1L, 384, 384, whi + O_CC2, wlo + O_CC2, 384, 128,
                                           b2H, b2L, 256, nullptr, 0, cc2_b, nullptr, 0);
    gemm_hmma<<<dim3(128, 2), 256, SMEM>>>(b2H, b2L, 256, 256, whi + O_CO1, wlo + O_CO1, 256, 256,
                                           coH, coL, 256, nullptr, 0, co1_b, co_bn, 1);
    gemm_hmma<<<dim3(128, 1), 256, SMEM>>>(coH, coL, 256, 256, whi + O_CO2, wlo + O_CO2, 256, 128,
                                           fuH + 32, fuL + 32, 160, nullptr, 0, co2_b, nullptr, 0);
    gemm_hmma<<<dim3(128, 2), 256, SMEM>>>(fuH, fuL, 160, 160, whi + O_DH1, wlo + O_DH1, 192, 160,
                                           d1H, d1L, 160, nullptr, 0, dh1_b, dh1_bn, 1);
    gemm_hmma<<<dim3(128, 2), 256, SMEM>>>(d1H, d1L, 160, 160, whi + O_DH2, wlo + O_DH2, 192, 160,
                                           d2H, d2L, 160, nullptr, 0, dh2_b, dh2_bn, 1);
    gemm_hmma<<<dim3(128, 1), 256, SMEM>>>(d2H, d2L, 160, 160, whi + O_DH3, wlo + O_DH3, 192, 128,
                                           fpH, fpL, 128, fpF, 128, dh3_b, nullptr, 0);
    gemm_hmma<<<dim3(128, 1), 256, SMEM>>>(fpH, fpL, 128, 128, whi + O_SH1, wlo + O_SH1, 128, 128,
                                           nullptr, nullptr, 0, s1F, 128, sh1_b, sh_bn, 1);

    // outputs: [pcd_xyz (NP*3)] [vote_scores (NP)] [vf (NP,128)]
    score_norm<<<NP / 8, 256>>>(s1F, fpF, sh2_w, sh2_b, out + NP * 3, out + NP * 3 + NP);
    cudaMemcpyAsync(out, pcd_xyz, NP * 3 * sizeof(float), cudaMemcpyDeviceToDevice, 0);
}